// round 1
// baseline (speedup 1.0000x reference)
#include <cuda_runtime.h>
#include <cstdint>
#include <cstddef>

#define B_ 2
#define C_ 256
#define H_ 128
#define W_ 128
#define Q_ 32768
#define HP 130
#define HW_ (H_*W_)

// ---------------- scratch (static device globals; no runtime allocation) ----------------
__device__ float g_feat_pad[(size_t)B_*HP*HP*C_];   // [B][130][130][256] zero-padded NHWC
__device__ float g_cf[(size_t)B_*HW_*512];          // [B][HW][512]: ch 0..255 = coef, 256..511 = freq
__device__ float g_wB[2304*512];                    // [tap*256+ic][512] packed conv weights
__device__ float g_cbias[512];

// ---------------- kernel 1: NCHW -> padded NHWC ----------------
__global__ void pad_kernel(const float* __restrict__ feat) {
    int id = blockIdx.x * 256 + threadIdx.x;
    const int total = B_*HP*HP*C_;
    if (id >= total) return;
    int c = id & 255;
    int rest = id >> 8;
    int xx = rest % HP; rest /= HP;
    int yy = rest % HP;
    int b  = rest / HP;
    float v = 0.f;
    if (yy >= 1 && yy <= H_ && xx >= 1 && xx <= W_) {
        v = feat[(((size_t)(b*C_ + c))*H_ + (yy-1))*W_ + (xx-1)];
    }
    g_feat_pad[id] = v;
}

// ---------------- kernel 2: weight repack ----------------
__global__ void reorg_kernel(const float* __restrict__ cw, const float* __restrict__ cb,
                             const float* __restrict__ fw, const float* __restrict__ fb) {
    int id = blockIdx.x * 256 + threadIdx.x;
    if (id < 512) g_cbias[id] = (id < 256) ? cb[id] : fb[id - 256];
    if (id >= 2304*512) return;
    int oc = id & 511;
    int k  = id >> 9;        // 0..2303
    int tap = k >> 8;        // 0..8
    int ic  = k & 255;
    float v = (oc < 256) ? cw[(oc*256 + ic)*9 + tap]
                         : fw[((oc-256)*256 + ic)*9 + tap];
    g_wB[id] = v;
}

// ---------------- kernel 3: fused dual conv as implicit GEMM ----------------
// block: 64 pixels (one row strip) x 64 out-channels, K = 9*256
__global__ __launch_bounds__(256) void conv_kernel() {
    __shared__ float As[16][64];
    __shared__ float Bs[16][64];
    const int oc0 = blockIdx.x * 64;          // 0..448
    const int x0  = blockIdx.y * 64;          // 0 or 64
    const int bz  = blockIdx.z;               // b*128 + y
    const int b = bz >> 7, y = bz & 127;
    const int t  = threadIdx.x;
    const int ty = t >> 4, tx = t & 15;       // 16x16 threads, 4x4 micro
    const int lm = t >> 2, kq = (t & 3) << 2; // A loader mapping

    float acc[4][4];
    #pragma unroll
    for (int i = 0; i < 4; ++i)
        #pragma unroll
        for (int j = 0; j < 4; ++j) acc[i][j] = 0.f;

    #pragma unroll 1
    for (int tap = 0; tap < 9; ++tap) {
        const int ky = tap / 3, kx = tap - ky*3;
        const float* gp  = g_feat_pad + ((size_t)((b*HP + y + ky)*HP + x0 + kx)) * C_;
        const float* wp0 = g_wB + (size_t)(tap*256)*512 + oc0;
        #pragma unroll 1
        for (int c = 0; c < 256; c += 16) {
            // stage A: 64 pixels x 16 ic  (coalesced float4 per pixel)
            float4 av = *(const float4*)(gp + lm*C_ + c + kq);
            As[kq+0][lm] = av.x; As[kq+1][lm] = av.y; As[kq+2][lm] = av.z; As[kq+3][lm] = av.w;
            // stage B: 16 k x 64 oc (coalesced)
            const float* wp = wp0 + (size_t)c * 512;
            #pragma unroll
            for (int i = 0; i < 4; ++i) {
                int idx = t + i*256;
                int kk = idx >> 6, n = idx & 63;
                Bs[kk][n] = wp[kk*512 + n];
            }
            __syncthreads();
            #pragma unroll
            for (int kk = 0; kk < 16; ++kk) {
                float4 a  = *(const float4*)&As[kk][ty << 2];
                float4 w4 = *(const float4*)&Bs[kk][tx << 2];
                acc[0][0]=fmaf(a.x,w4.x,acc[0][0]); acc[0][1]=fmaf(a.x,w4.y,acc[0][1]);
                acc[0][2]=fmaf(a.x,w4.z,acc[0][2]); acc[0][3]=fmaf(a.x,w4.w,acc[0][3]);
                acc[1][0]=fmaf(a.y,w4.x,acc[1][0]); acc[1][1]=fmaf(a.y,w4.y,acc[1][1]);
                acc[1][2]=fmaf(a.y,w4.z,acc[1][2]); acc[1][3]=fmaf(a.y,w4.w,acc[1][3]);
                acc[2][0]=fmaf(a.z,w4.x,acc[2][0]); acc[2][1]=fmaf(a.z,w4.y,acc[2][1]);
                acc[2][2]=fmaf(a.z,w4.z,acc[2][2]); acc[2][3]=fmaf(a.z,w4.w,acc[2][3]);
                acc[3][0]=fmaf(a.w,w4.x,acc[3][0]); acc[3][1]=fmaf(a.w,w4.y,acc[3][1]);
                acc[3][2]=fmaf(a.w,w4.z,acc[3][2]); acc[3][3]=fmaf(a.w,w4.w,acc[3][3]);
            }
            __syncthreads();
        }
    }
    float4 bb = *(const float4*)(g_cbias + oc0 + (tx << 2));
    #pragma unroll
    for (int i = 0; i < 4; ++i) {
        int m = (ty << 2) + i;
        float4 o;
        o.x = acc[i][0] + bb.x; o.y = acc[i][1] + bb.y;
        o.z = acc[i][2] + bb.z; o.w = acc[i][3] + bb.w;
        *(float4*)(g_cf + ((size_t)(b*HW_ + y*W_ + x0 + m))*512 + oc0 + (tx << 2)) = o;
    }
}

// ---------------- kernel 4: fused gather + sinusoid + MLP + ensemble ----------------
// block = 16 points x 4 shifts = 64 MLP rows; 256 threads
#define XSS 260
__global__ __launch_bounds__(256) void point_kernel(
        const float* __restrict__ pc,
        const float* __restrict__ phase_w,
        const float* __restrict__ w0, const float* __restrict__ b0,
        const float* __restrict__ w1, const float* __restrict__ b1,
        const float* __restrict__ w2, const float* __restrict__ b2,
        const float* __restrict__ w3, const float* __restrict__ b3,
        const float* __restrict__ coarse,
        float* __restrict__ out) {
    extern __shared__ float sm[];
    float* Xs     = sm;                 // 64*260
    float* Ys     = Xs + 64*XSS;        // 64*260
    float* Ws     = Ys + 64*XSS;        // 16*256
    float* ph     = Ws + 16*256;        // 2*128
    float* s_rel0 = ph + 256;           // 64
    float* s_rel1 = s_rel0 + 64;        // 64
    float* s_area = s_rel1 + 64;        // 64
    int*   s_pix  = (int*)(s_area + 64);   // 64
    int*   s_phof = s_pix + 64;            // 64
    float* w3s    = (float*)(s_phof + 64); // 514 (w3 + b3)
    float* s_pr   = w3s + 514;             // 128

    const int t  = threadIdx.x;
    const int g0 = blockIdx.x * 16;

    // phase vectors (two variants: q<2 uses cell*2/32, else cell=1)
    if (t < 128) {
        float p0 = phase_w[2*t], p1 = phase_w[2*t+1];
        ph[t]       = fmaf(8.f,   p0, 8.f*p1);
        ph[128 + t] = fmaf(128.f, p0, 128.f*p1);
    }
    for (int i = t; i < 514; i += 256)
        w3s[i] = (i < 512) ? w3[i] : b3[i - 512];

    // ---- stage 1: per-row index / rel / area ----
    if (t < 64) {
        const int p_local = t >> 2, s = t & 3;   // s: 0=(-1,-1) 1=(-1,+1) 2=(+1,-1) 3=(+1,+1)
        const int g = g0 + p_local;
        const int q = g & (Q_ - 1);
        const float pc0 = pc[2*g], pc1 = pc[2*g + 1];
        const float SH_P = (float)( 1.0/128.0 + 1e-6);
        const float SH_M = (float)(-1.0/128.0 + 1e-6);
        const float LO = (float)(-1.0 + 1e-6), HI = (float)(1.0 - 1e-6);
        float cy = pc0 + ((s >= 2) ? SH_P : SH_M);
        float cx = pc1 + ((s & 1) ? SH_P : SH_M);
        cy = fminf(fmaxf(cy, LO), HI);
        cx = fminf(fmaxf(cx, LO), HI);
        int iy = (int)rintf(((cy + 1.f)*128.f - 1.f)*0.5f);  // round half-even, matches jnp.round
        int ix = (int)rintf(((cx + 1.f)*128.f - 1.f)*0.5f);
        iy = min(max(iy, 0), 127); ix = min(max(ix, 0), 127);
        float qcy = -0.9921875f + 0.015625f*(float)iy;       // exact pixel centers
        float qcx = -0.9921875f + 0.015625f*(float)ix;
        float rel0 = (pc0 - qcy)*128.f;
        float rel1 = (pc1 - qcx)*128.f;
        s_pix[t]  = iy*W_ + ix;
        s_rel0[t] = rel0;  s_rel1[t] = rel1;
        s_area[t] = fabsf(rel0*rel1) + 1e-9f;
        s_phof[t] = (q < 2) ? 0 : 128;
    }
    __syncthreads();

    // ---- stage 2: gather + sinusoidal features into Xs ----
    {
        const int w = t >> 5, lane = t & 31;
        #pragma unroll 1
        for (int rr = 0; rr < 8; ++rr) {
            const int r = w*8 + rr;
            const int g = g0 + (r >> 2);
            const int b = g >> 15;
            const float* base = g_cf + ((size_t)(b*HW_ + s_pix[r])) * 512;
            const float rel0 = s_rel0[r], rel1 = s_rel1[r];
            const float* php = ph + s_phof[r];
            #pragma unroll
            for (int i = 0; i < 4; ++i) {
                const int k = lane + 32*i;
                float2 f2 = *(const float2*)(base + 256 + 2*k);
                float qf = fmaf(f2.x, rel0, fmaf(f2.y, rel1, php[k]));
                float sv, cv;
                sincospif(qf, &sv, &cv);
                Xs[r*XSS + k]        = base[k]       * cv;
                Xs[r*XSS + 128 + k]  = base[128 + k] * sv;
            }
        }
    }
    __syncthreads();

    // ---- stage 3: 3x fused relu-GEMM, fully shared-memory resident ----
    const int ty = t >> 5, tx = t & 31;  // warp-uniform ty => broadcast A reads
    float* inb = Xs; float* outb = Ys;
    #pragma unroll 1
    for (int L = 0; L < 3; ++L) {
        const float* Wg = (L == 0) ? w0 : (L == 1) ? w1 : w2;
        const float* bg = (L == 0) ? b0 : (L == 1) ? b1 : b2;
        float acc[8][8];
        #pragma unroll
        for (int i = 0; i < 8; ++i)
            #pragma unroll
            for (int j = 0; j < 8; ++j) acc[i][j] = 0.f;
        #pragma unroll 1
        for (int k0 = 0; k0 < 256; k0 += 16) {
            #pragma unroll
            for (int i = 0; i < 4; ++i) {
                int idx = t + i*256;
                int kk = idx >> 6, nc = (idx & 63) << 2;
                *(float4*)&Ws[kk*256 + nc] = *(const float4*)&Wg[(k0 + kk)*256 + nc];
            }
            __syncthreads();
            #pragma unroll
            for (int kk = 0; kk < 16; ++kk) {
                float a[8];
                #pragma unroll
                for (int i = 0; i < 8; ++i) a[i] = inb[(ty*8 + i)*XSS + k0 + kk];
                float4 wA = *(const float4*)&Ws[kk*256 + tx*8];
                float4 wC = *(const float4*)&Ws[kk*256 + tx*8 + 4];
                #pragma unroll
                for (int i = 0; i < 8; ++i) {
                    acc[i][0]=fmaf(a[i],wA.x,acc[i][0]); acc[i][1]=fmaf(a[i],wA.y,acc[i][1]);
                    acc[i][2]=fmaf(a[i],wA.z,acc[i][2]); acc[i][3]=fmaf(a[i],wA.w,acc[i][3]);
                    acc[i][4]=fmaf(a[i],wC.x,acc[i][4]); acc[i][5]=fmaf(a[i],wC.y,acc[i][5]);
                    acc[i][6]=fmaf(a[i],wC.z,acc[i][6]); acc[i][7]=fmaf(a[i],wC.w,acc[i][7]);
                }
            }
            __syncthreads();
        }
        #pragma unroll
        for (int i = 0; i < 8; ++i)
            #pragma unroll
            for (int j = 0; j < 8; ++j) {
                float v = acc[i][j] + bg[tx*8 + j];
                outb[(ty*8 + i)*XSS + tx*8 + j] = fmaxf(v, 0.f);
            }
        __syncthreads();
        float* tmp = inb; inb = outb; outb = tmp;
    }

    // ---- final 256->2 layer ----
    if (t < 128) {
        const int r = t >> 1, c = t & 1;
        const float* row = inb + r*XSS;
        float sum = w3s[512 + c];
        #pragma unroll 8
        for (int i = 0; i < 256; ++i) sum = fmaf(row[i], w3s[2*i + c], sum);
        s_pr[2*r + c] = sum;
    }
    __syncthreads();

    // ---- local-ensemble combine (diagonal area swap) + coarse residual ----
    if (t < 32) {
        const int p = t >> 1, c = t & 1;
        const int rb = p*4;
        float a0 = s_area[rb+0], a1 = s_area[rb+1], a2 = s_area[rb+2], a3 = s_area[rb+3];
        float tot = a0 + a1 + a2 + a3;
        float v = s_pr[2*(rb+0)+c]*a3 + s_pr[2*(rb+1)+c]*a2
                + s_pr[2*(rb+2)+c]*a1 + s_pr[2*(rb+3)+c]*a0;
        v /= tot;
        const int g = g0 + p;
        const int b = g >> 15, q = g & (Q_ - 1);
        const int oidx = (b*2 + c)*Q_ + q;
        out[oidx] = v + coarse[oidx];
    }
}

// ---------------- launch ----------------
extern "C" void kernel_launch(void* const* d_in, const int* in_sizes, int n_in,
                              void* d_out, int out_size) {
    const float* feat    = (const float*)d_in[0];
    const float* pcoords = (const float*)d_in[1];
    const float* coarse  = (const float*)d_in[2];
    // d_in[3] = coarse_sem_seg_logits: only its (32,32) shape matters -> constants
    const float* coef_w  = (const float*)d_in[4];
    const float* coef_b  = (const float*)d_in[5];
    const float* freq_w  = (const float*)d_in[6];
    const float* freq_b  = (const float*)d_in[7];
    const float* phase_w = (const float*)d_in[8];
    const float* w0 = (const float*)d_in[9];
    const float* b0 = (const float*)d_in[10];
    const float* w1 = (const float*)d_in[11];
    const float* b1 = (const float*)d_in[12];
    const float* w2 = (const float*)d_in[13];
    const float* b2 = (const float*)d_in[14];
    const float* w3 = (const float*)d_in[15];
    const float* b3 = (const float*)d_in[16];
    float* out = (float*)d_out;

    pad_kernel<<<(B_*HP*HP*C_ + 255)/256, 256>>>(feat);
    reorg_kernel<<<(2304*512 + 255)/256, 256>>>(coef_w, coef_b, freq_w, freq_b);

    dim3 cgrid(512/64, W_/64, B_*H_);
    conv_kernel<<<cgrid, 256>>>();

    const size_t PSMEM = ((size_t)(64*XSS*2 + 16*256 + 256 + 64*5 + 514 + 128)) * 4 + 64;
    cudaFuncSetAttribute(point_kernel, cudaFuncAttributeMaxDynamicSharedMemorySize, (int)PSMEM);
    point_kernel<<<(B_*Q_)/16, 256, PSMEM>>>(pcoords, phase_w,
                                             w0, b0, w1, b1, w2, b2, w3, b3,
                                             coarse, out);
}

// round 2
// speedup vs baseline: 2.2749x; 2.2749x over previous
#include <cuda_runtime.h>
#include <cuda_bf16.h>
#include <cstdint>
#include <cstddef>

#define B_ 2
#define C_ 256
#define H_ 128
#define W_ 128
#define Q_ 32768
#define HP 130
#define HW_ (H_*W_)

// ---------------- static device scratch ----------------
__device__ __align__(16) __nv_bfloat16 g_Ah[(size_t)B_*HP*HP*C_];   // padded NHWC hi
__device__ __align__(16) __nv_bfloat16 g_Al[(size_t)B_*HP*HP*C_];   // padded NHWC lo
__device__ __align__(16) __nv_bfloat16 g_Wth[512*2304];             // conv W^T [oc][k] hi
__device__ __align__(16) __nv_bfloat16 g_Wtl[512*2304];             // lo
__device__ __align__(16) __nv_bfloat16 g_Mth[3*256*256];            // mlp W^T [l][n][k] hi
__device__ __align__(16) __nv_bfloat16 g_Mtl[3*256*256];            // lo
__device__ float g_cbias[512];
__device__ __align__(16) float g_cf[(size_t)B_*HW_*512];            // conv out [b][pix][512] fp32

// ---------------- helpers ----------------
__device__ __forceinline__ uint32_t smem_u32(const void* p){
    return (uint32_t)__cvta_generic_to_shared(p);
}
__device__ __forceinline__ void ldsm4(uint32_t& r0,uint32_t& r1,uint32_t& r2,uint32_t& r3,uint32_t a){
    asm volatile("ldmatrix.sync.aligned.m8n8.x4.shared.b16 {%0,%1,%2,%3},[%4];"
        :"=r"(r0),"=r"(r1),"=r"(r2),"=r"(r3):"r"(a));
}
__device__ __forceinline__ void cp16(uint32_t d, const void* s){
    asm volatile("cp.async.ca.shared.global [%0],[%1],16;"::"r"(d),"l"(s));
}
__device__ __forceinline__ void cp_commit(){ asm volatile("cp.async.commit_group;"); }
__device__ __forceinline__ void mma16816(float* c, const uint32_t* a, const uint32_t* b){
    asm volatile("mma.sync.aligned.m16n8k16.row.col.f32.bf16.bf16.f32 "
        "{%0,%1,%2,%3},{%4,%5,%6,%7},{%8,%9},{%0,%1,%2,%3};"
        : "+f"(c[0]),"+f"(c[1]),"+f"(c[2]),"+f"(c[3])
        : "r"(a[0]),"r"(a[1]),"r"(a[2]),"r"(a[3]),"r"(b[0]),"r"(b[1]));
}
__device__ __forceinline__ uint32_t pack_hi(float2 v){
    __nv_bfloat162 h = __floats2bfloat162_rn(v.x, v.y);
    return *reinterpret_cast<uint32_t*>(&h);
}
__device__ __forceinline__ uint32_t pack_lo(float2 v, uint32_t hb){
    __nv_bfloat162 h = *reinterpret_cast<__nv_bfloat162*>(&hb);
    __nv_bfloat162 l = __floats2bfloat162_rn(v.x - __bfloat162float(h.x),
                                             v.y - __bfloat162float(h.y));
    return *reinterpret_cast<uint32_t*>(&l);
}

// ---------------- prep kernels ----------------
__global__ void prep_feat(const float* __restrict__ feat){
    int id = blockIdx.x*256 + threadIdx.x;
    if (id >= B_*HP*HP*C_) return;
    int c = id & 255; int rest = id >> 8;
    int xx = rest % HP; rest /= HP;
    int yy = rest % HP; int b = rest / HP;
    float v = 0.f;
    if (yy >= 1 && yy <= H_ && xx >= 1 && xx <= W_)
        v = feat[(((size_t)(b*C_ + c))*H_ + (yy-1))*W_ + (xx-1)];
    __nv_bfloat16 h = __float2bfloat16(v);
    g_Ah[id] = h;
    g_Al[id] = __float2bfloat16(v - __bfloat162float(h));
}

__global__ void prep_wconv(const float* __restrict__ cw, const float* __restrict__ cb,
                           const float* __restrict__ fw, const float* __restrict__ fb){
    int id = blockIdx.x*256 + threadIdx.x;
    if (id < 512) g_cbias[id] = (id < 256) ? cb[id] : fb[id-256];
    if (id >= 512*2304) return;
    int oc = id / 2304, k = id % 2304;
    int tap = k >> 8, ic = k & 255;
    float v = (oc < 256) ? cw[(oc*256 + ic)*9 + tap]
                         : fw[((oc-256)*256 + ic)*9 + tap];
    __nv_bfloat16 h = __float2bfloat16(v);
    g_Wth[id] = h;
    g_Wtl[id] = __float2bfloat16(v - __bfloat162float(h));
}

__global__ void prep_wmlp(const float* __restrict__ w0, const float* __restrict__ w1,
                          const float* __restrict__ w2){
    int id = blockIdx.x*256 + threadIdx.x;
    if (id >= 3*65536) return;
    int l = id >> 16, r = id & 65535;
    int n = r >> 8, k = r & 255;
    const float* w = (l==0) ? w0 : (l==1) ? w1 : w2;
    float v = w[k*256 + n];
    __nv_bfloat16 h = __float2bfloat16(v);
    g_Mth[id] = h;
    g_Mtl[id] = __float2bfloat16(v - __bfloat162float(h));
}

// ---------------- conv: dual 3x3 conv as implicit split-bf16 tensor GEMM ----------------
// block: 128 pixels (one image row) x 128 oc; K = 9*256 in steps of 32
#define CARR (128*40)       // bf16 elems per array per stage
#define CSTG (4*CARR)       // Ah,Al,Bh,Bl
__global__ __launch_bounds__(256) void conv_mma_kernel(){
    extern __shared__ __align__(16) __nv_bfloat16 cs[];   // [2][4][128*40]
    const int t = threadIdx.x, warp = t>>5, lane = t&31;
    const int oc0 = blockIdx.x*128, y = blockIdx.y, b = blockIdx.z;
    const int m0 = (warp>>2)*64, n0 = (warp&3)*32;

    float acc[4][4][4];
    #pragma unroll
    for (int i=0;i<4;++i)
        #pragma unroll
        for (int j=0;j<4;++j)
            #pragma unroll
            for (int q=0;q<4;++q) acc[i][j][q] = 0.f;

    auto issue = [&](int s, int stg){
        const int tap = s >> 3, sub = s & 7;
        const int ky = tap/3, kx = tap - ky*3;
        const int k0 = tap*256 + sub*32;
        __nv_bfloat16* dstb = cs + stg*CSTG;
        #pragma unroll
        for (int j=0;j<8;++j){
            int cid = t + j*256;
            int arr = cid >> 9, w = cid & 511, row = w >> 2, c = w & 3;
            uint32_t dst = smem_u32(dstb + arr*CARR + row*40 + c*8);
            const __nv_bfloat16* src;
            if (arr == 0)      src = g_Ah + ((size_t)((b*HP + y+ky)*HP + row+kx))*C_ + sub*32 + c*8;
            else if (arr == 1) src = g_Al + ((size_t)((b*HP + y+ky)*HP + row+kx))*C_ + sub*32 + c*8;
            else if (arr == 2) src = g_Wth + (size_t)(oc0+row)*2304 + k0 + c*8;
            else               src = g_Wtl + (size_t)(oc0+row)*2304 + k0 + c*8;
            cp16(dst, src);
        }
        cp_commit();
    };

    issue(0, 0);
    for (int s = 0; s < 72; ++s){
        const int stg = s & 1;
        if (s+1 < 72) issue(s+1, (s+1)&1);
        if (s+1 < 72) asm volatile("cp.async.wait_group 1;");
        else          asm volatile("cp.async.wait_group 0;");
        __syncthreads();
        const __nv_bfloat16* Ah = cs + stg*CSTG;
        const __nv_bfloat16* Al = Ah + CARR;
        const __nv_bfloat16* Bh = Al + CARR;
        const __nv_bfloat16* Bl = Bh + CARR;
        const int rsel = lane & 15, kgrp = (lane >> 4)*8;
        #pragma unroll
        for (int k16 = 0; k16 < 32; k16 += 16){
            uint32_t ah[4][4], al[4][4], bh[4][2], bl[4][2];
            #pragma unroll
            for (int mi=0;mi<4;++mi){
                uint32_t a0 = smem_u32(Ah + (m0+mi*16+rsel)*40 + k16 + kgrp);
                ldsm4(ah[mi][0],ah[mi][1],ah[mi][2],ah[mi][3], a0);
                uint32_t a1 = smem_u32(Al + (m0+mi*16+rsel)*40 + k16 + kgrp);
                ldsm4(al[mi][0],al[mi][1],al[mi][2],al[mi][3], a1);
            }
            #pragma unroll
            for (int nj=0;nj<2;++nj){
                uint32_t r0,r1,r2,r3;
                uint32_t a0 = smem_u32(Bh + (n0+nj*16+rsel)*40 + k16 + kgrp);
                ldsm4(r0,r1,r2,r3,a0);
                bh[2*nj][0]=r0; bh[2*nj][1]=r2; bh[2*nj+1][0]=r1; bh[2*nj+1][1]=r3;
                uint32_t a1 = smem_u32(Bl + (n0+nj*16+rsel)*40 + k16 + kgrp);
                ldsm4(r0,r1,r2,r3,a1);
                bl[2*nj][0]=r0; bl[2*nj][1]=r2; bl[2*nj+1][0]=r1; bl[2*nj+1][1]=r3;
            }
            #pragma unroll
            for (int mi=0;mi<4;++mi)
                #pragma unroll
                for (int ni=0;ni<4;++ni){
                    mma16816(acc[mi][ni], ah[mi], bh[ni]);
                    mma16816(acc[mi][ni], ah[mi], bl[ni]);
                    mma16816(acc[mi][ni], al[mi], bh[ni]);
                }
        }
        __syncthreads();
    }

    // epilogue: + bias, store fp32 pixel-major
    #pragma unroll
    for (int mi=0;mi<4;++mi){
        const int x = m0 + mi*16 + (lane>>2);
        #pragma unroll
        for (int ni=0;ni<4;++ni){
            const int col = oc0 + n0 + ni*8 + (lane&3)*2;
            float2 bb = *(const float2*)&g_cbias[col];
            float* o0 = g_cf + ((size_t)(b*HW_ + y*W_ + x))*512 + col;
            float* o1 = g_cf + ((size_t)(b*HW_ + y*W_ + x + 8))*512 + col;
            *(float2*)o0 = make_float2(acc[mi][ni][0]+bb.x, acc[mi][ni][1]+bb.y);
            *(float2*)o1 = make_float2(acc[mi][ni][2]+bb.x, acc[mi][ni][3]+bb.y);
        }
    }
}

// ---------------- point kernel: gather + sinusoid + split-bf16 tensor MLP ----------------
// block = 16 points x 4 shifts = 64 rows; 256 threads; activations fp32 in smem
#define XS 260
#define WARR (256*40)       // bf16 elems per comp per stage
#define WSTG (2*WARR)
__global__ __launch_bounds__(256) void point_mma_kernel(
        const float* __restrict__ pc,
        const float* __restrict__ phase_w,
        const float* __restrict__ b0, const float* __restrict__ b1,
        const float* __restrict__ b2,
        const float* __restrict__ w3, const float* __restrict__ b3,
        const float* __restrict__ coarse,
        float* __restrict__ out) {
    extern __shared__ __align__(16) float sm[];
    float* X = sm;                                          // 64*XS floats
    __nv_bfloat16* Wt = (__nv_bfloat16*)(X + 64*XS);        // 2 stages * WSTG bf16
    float* misc  = (float*)(Wt + 2*WSTG);
    float* ph     = misc;                // 256
    float* s_rel0 = ph + 256;            // 64
    float* s_rel1 = s_rel0 + 64;         // 64
    float* s_area = s_rel1 + 64;         // 64
    int*   s_pix  = (int*)(s_area + 64); // 64
    int*   s_phof = s_pix + 64;          // 64
    float* w3s    = (float*)(s_phof + 64); // 514
    float* s_pr   = w3s + 514;             // 128

    const int t = threadIdx.x, warp = t>>5, lane = t&31;
    const int g0 = blockIdx.x * 16;
    const int m0 = (warp>>2)*32, n0 = (warp&3)*64;

    // constants into smem
    if (t < 128) {
        float p0 = phase_w[2*t], p1 = phase_w[2*t+1];
        ph[t]       = fmaf(8.f,   p0, 8.f*p1);
        ph[128 + t] = fmaf(128.f, p0, 128.f*p1);
    }
    for (int i = t; i < 514; i += 256)
        w3s[i] = (i < 512) ? w3[i] : b3[i - 512];

    // stage 1: per-row pixel index / rel / area
    if (t < 64) {
        const int p_local = t >> 2, s = t & 3;
        const int g = g0 + p_local;
        const int q = g & (Q_ - 1);
        const float pc0 = pc[2*g], pc1 = pc[2*g + 1];
        const float SH_P = (float)( 1.0/128.0 + 1e-6);
        const float SH_M = (float)(-1.0/128.0 + 1e-6);
        const float LO = (float)(-1.0 + 1e-6), HI = (float)(1.0 - 1e-6);
        float cy = pc0 + ((s >= 2) ? SH_P : SH_M);
        float cx = pc1 + ((s & 1) ? SH_P : SH_M);
        cy = fminf(fmaxf(cy, LO), HI);
        cx = fminf(fmaxf(cx, LO), HI);
        int iy = (int)rintf(((cy + 1.f)*128.f - 1.f)*0.5f);
        int ix = (int)rintf(((cx + 1.f)*128.f - 1.f)*0.5f);
        iy = min(max(iy, 0), 127); ix = min(max(ix, 0), 127);
        float qcy = -0.9921875f + 0.015625f*(float)iy;
        float qcx = -0.9921875f + 0.015625f*(float)ix;
        float rel0 = (pc0 - qcy)*128.f;
        float rel1 = (pc1 - qcx)*128.f;
        s_pix[t]  = iy*W_ + ix;
        s_rel0[t] = rel0;  s_rel1[t] = rel1;
        s_area[t] = fabsf(rel0*rel1) + 1e-9f;
        s_phof[t] = (q < 2) ? 0 : 128;
    }
    __syncthreads();

    // prefetch MLP layer0/step0 weights early (overlaps with gather)
    auto wissue = [&](int g, int stg){
        const int L = g >> 3, s = g & 7;
        __nv_bfloat16* dstb = Wt + stg*WSTG;
        const __nv_bfloat16* srch = g_Mth + L*65536;
        const __nv_bfloat16* srcl = g_Mtl + L*65536;
        #pragma unroll
        for (int j=0;j<8;++j){
            int cid = t + j*256;
            int comp = cid >> 10, w = cid & 1023, row = w >> 2, c = w & 3;
            uint32_t dst = smem_u32(dstb + comp*WARR + row*40 + c*8);
            const __nv_bfloat16* src = (comp ? srcl : srch) + row*256 + s*32 + c*8;
            cp16(dst, src);
        }
        cp_commit();
    };
    wissue(0, 0);

    // stage 2: gather + sinusoidal features into X (fp32)
    {
        #pragma unroll 1
        for (int rr = 0; rr < 8; ++rr) {
            const int r = warp*8 + rr;
            const int g = g0 + (r >> 2);
            const int bb = g >> 15;
            const float* base = g_cf + ((size_t)(bb*HW_ + s_pix[r])) * 512;
            const float rel0 = s_rel0[r], rel1 = s_rel1[r];
            const float* php = ph + s_phof[r];
            #pragma unroll
            for (int i = 0; i < 4; ++i) {
                const int k = lane + 32*i;
                float2 f2 = *(const float2*)(base + 256 + 2*k);
                float qf = fmaf(f2.x, rel0, fmaf(f2.y, rel1, php[k]));
                float sv, cv;
                sincospif(qf, &sv, &cv);
                X[r*XS + k]       = base[k]       * cv;
                X[r*XS + 128 + k] = base[128 + k] * sv;
            }
        }
    }

    // stage 3: 3 layers of split-bf16 tensor GEMM, K staged by 32
    float acc[2][8][4];
    const int rA = lane >> 2, kA = (lane & 3) << 1;
    const int rsel = lane & 15, kgrp = (lane >> 4)*8;
    for (int g = 0; g < 24; ++g){
        const int L = g >> 3, s = g & 7, stg = g & 1;
        if (s == 0){
            #pragma unroll
            for (int i=0;i<2;++i)
                #pragma unroll
                for (int j=0;j<8;++j)
                    #pragma unroll
                    for (int q=0;q<4;++q) acc[i][j][q] = 0.f;
        }
        if (g+1 < 24) wissue(g+1, (g+1)&1);
        if (g+1 < 24) asm volatile("cp.async.wait_group 1;");
        else          asm volatile("cp.async.wait_group 0;");
        __syncthreads();

        const __nv_bfloat16* WH = Wt + stg*WSTG;
        const __nv_bfloat16* WL = WH + WARR;
        const int k0 = s*32;
        #pragma unroll
        for (int kh = 0; kh < 2; ++kh){
            const int k16 = k0 + kh*16;
            uint32_t AH[2][4], AL[2][4];
            #pragma unroll
            for (int mi=0;mi<2;++mi){
                const float* px = X + (m0 + mi*16 + rA)*XS + k16 + kA;
                float2 x0 = *(const float2*)px;
                float2 x1 = *(const float2*)(px + 8*XS);
                float2 x2 = *(const float2*)(px + 8);
                float2 x3 = *(const float2*)(px + 8*XS + 8);
                AH[mi][0] = pack_hi(x0); AL[mi][0] = pack_lo(x0, AH[mi][0]);
                AH[mi][1] = pack_hi(x1); AL[mi][1] = pack_lo(x1, AH[mi][1]);
                AH[mi][2] = pack_hi(x2); AL[mi][2] = pack_lo(x2, AH[mi][2]);
                AH[mi][3] = pack_hi(x3); AL[mi][3] = pack_lo(x3, AH[mi][3]);
            }
            uint32_t BH[8][2], BL[8][2];
            #pragma unroll
            for (int nj=0;nj<4;++nj){
                uint32_t r0,r1,r2,r3;
                uint32_t a0 = smem_u32(WH + (n0+nj*16+rsel)*40 + kh*16 + kgrp);
                ldsm4(r0,r1,r2,r3,a0);
                BH[2*nj][0]=r0; BH[2*nj][1]=r2; BH[2*nj+1][0]=r1; BH[2*nj+1][1]=r3;
                uint32_t a1 = smem_u32(WL + (n0+nj*16+rsel)*40 + kh*16 + kgrp);
                ldsm4(r0,r1,r2,r3,a1);
                BL[2*nj][0]=r0; BL[2*nj][1]=r2; BL[2*nj+1][0]=r1; BL[2*nj+1][1]=r3;
            }
            #pragma unroll
            for (int mi=0;mi<2;++mi)
                #pragma unroll
                for (int ni=0;ni<8;++ni){
                    mma16816(acc[mi][ni], AH[mi], BH[ni]);
                    mma16816(acc[mi][ni], AH[mi], BL[ni]);
                    mma16816(acc[mi][ni], AL[mi], BH[ni]);
                }
        }
        __syncthreads();

        if (s == 7){
            // layer epilogue: relu(acc + bias) back into X (all reads done via sync above)
            const float* bg = (L==0) ? b0 : (L==1) ? b1 : b2;
            #pragma unroll
            for (int mi=0;mi<2;++mi){
                const int r = m0 + mi*16 + (lane>>2);
                #pragma unroll
                for (int ni=0;ni<8;++ni){
                    const int c = n0 + ni*8 + (lane&3)*2;
                    float2 bb = *(const float2*)&bg[c];
                    *(float2*)&X[r*XS + c] =
                        make_float2(fmaxf(acc[mi][ni][0]+bb.x, 0.f),
                                    fmaxf(acc[mi][ni][1]+bb.y, 0.f));
                    *(float2*)&X[(r+8)*XS + c] =
                        make_float2(fmaxf(acc[mi][ni][2]+bb.x, 0.f),
                                    fmaxf(acc[mi][ni][3]+bb.y, 0.f));
                }
            }
            __syncthreads();
        }
    }

    // final 256->2 layer (fp32 FFMA, tiny)
    if (t < 128) {
        const int r = t >> 1, c = t & 1;
        const float* row = X + r*XS;
        float sum = w3s[512 + c];
        #pragma unroll 8
        for (int i = 0; i < 256; ++i) sum = fmaf(row[i], w3s[2*i + c], sum);
        s_pr[2*r + c] = sum;
    }
    __syncthreads();

    // local-ensemble combine + coarse residual
    if (t < 32) {
        const int p = t >> 1, c = t & 1;
        const int rb = p*4;
        float a0 = s_area[rb+0], a1 = s_area[rb+1], a2 = s_area[rb+2], a3 = s_area[rb+3];
        float tot = a0 + a1 + a2 + a3;
        float v = s_pr[2*(rb+0)+c]*a3 + s_pr[2*(rb+1)+c]*a2
                + s_pr[2*(rb+2)+c]*a1 + s_pr[2*(rb+3)+c]*a0;
        v /= tot;
        const int g = g0 + p;
        const int bb = g >> 15, q = g & (Q_ - 1);
        const int oidx = (bb*2 + c)*Q_ + q;
        out[oidx] = v + coarse[oidx];
    }
}

// ---------------- launch ----------------
extern "C" void kernel_launch(void* const* d_in, const int* in_sizes, int n_in,
                              void* d_out, int out_size) {
    const float* feat    = (const float*)d_in[0];
    const float* pcoords = (const float*)d_in[1];
    const float* coarse  = (const float*)d_in[2];
    const float* coef_w  = (const float*)d_in[4];
    const float* coef_b  = (const float*)d_in[5];
    const float* freq_w  = (const float*)d_in[6];
    const float* freq_b  = (const float*)d_in[7];
    const float* phase_w = (const float*)d_in[8];
    const float* w0 = (const float*)d_in[9];   (void)w0;
    const float* b0 = (const float*)d_in[10];
    const float* w1 = (const float*)d_in[11];  (void)w1;
    const float* b1 = (const float*)d_in[12];
    const float* w2 = (const float*)d_in[13];  (void)w2;
    const float* b2 = (const float*)d_in[14];
    const float* w3 = (const float*)d_in[15];
    const float* b3 = (const float*)d_in[16];
    float* out = (float*)d_out;

    prep_feat<<<(B_*HP*HP*C_ + 255)/256, 256>>>(feat);
    prep_wconv<<<(512*2304 + 255)/256, 256>>>(coef_w, coef_b, freq_w, freq_b);
    prep_wmlp<<<(3*65536 + 255)/256, 256>>>((const float*)d_in[9], (const float*)d_in[11],
                                            (const float*)d_in[13]);

    const int CSMEM = 2*CSTG*2;  // 81920 B
    cudaFuncSetAttribute(conv_mma_kernel, cudaFuncAttributeMaxDynamicSharedMemorySize, CSMEM);
    conv_mma_kernel<<<dim3(4, 128, 2), 256, CSMEM>>>();

    const int PSMEM = 64*XS*4 + 2*WSTG*2 + (256 + 64*5 + 514 + 128)*4 + 32;
    cudaFuncSetAttribute(point_mma_kernel, cudaFuncAttributeMaxDynamicSharedMemorySize, PSMEM);
    point_mma_kernel<<<(B_*Q_)/16, 256, PSMEM>>>(pcoords, phase_w,
                                                 b0, b1, b2, w3, b3,
                                                 coarse, out);
}

// round 3
// speedup vs baseline: 2.4369x; 1.0712x over previous
#include <cuda_runtime.h>
#include <cuda_bf16.h>
#include <cstdint>
#include <cstddef>

#define B_ 2
#define C_ 256
#define H_ 128
#define W_ 128
#define Q_ 32768
#define HP 130
#define HW_ (H_*W_)

// ---------------- static device scratch ----------------
__device__ __align__(16) __nv_bfloat16 g_Ah[(size_t)B_*HP*HP*C_];   // padded NHWC hi
__device__ __align__(16) __nv_bfloat16 g_Al[(size_t)B_*HP*HP*C_];   // padded NHWC lo
__device__ __align__(16) __nv_bfloat16 g_Wth[512*2304];             // conv W^T [oc][k] hi
__device__ __align__(16) __nv_bfloat16 g_Wtl[512*2304];             // lo
__device__ __align__(16) __nv_bfloat16 g_Mth[3*256*256];            // mlp W^T [l][n][k] hi
__device__ __align__(16) __nv_bfloat16 g_Mtl[3*256*256];            // lo
__device__ float g_cbias[512];
__device__ __align__(16) float g_cf[(size_t)B_*HW_*512];            // conv out [b][pix][512] fp32

// ---------------- helpers ----------------
__device__ __forceinline__ uint32_t smem_u32(const void* p){
    return (uint32_t)__cvta_generic_to_shared(p);
}
__device__ __forceinline__ void ldsm4(uint32_t& r0,uint32_t& r1,uint32_t& r2,uint32_t& r3,uint32_t a){
    asm volatile("ldmatrix.sync.aligned.m8n8.x4.shared.b16 {%0,%1,%2,%3},[%4];"
        :"=r"(r0),"=r"(r1),"=r"(r2),"=r"(r3):"r"(a));
}
__device__ __forceinline__ void cp16(uint32_t d, const void* s){
    asm volatile("cp.async.ca.shared.global [%0],[%1],16;"::"r"(d),"l"(s));
}
__device__ __forceinline__ void cp_commit(){ asm volatile("cp.async.commit_group;"); }
__device__ __forceinline__ void mma16816(float* c, const uint32_t* a, const uint32_t* b){
    asm volatile("mma.sync.aligned.m16n8k16.row.col.f32.bf16.bf16.f32 "
        "{%0,%1,%2,%3},{%4,%5,%6,%7},{%8,%9},{%0,%1,%2,%3};"
        : "+f"(c[0]),"+f"(c[1]),"+f"(c[2]),"+f"(c[3])
        : "r"(a[0]),"r"(a[1]),"r"(a[2]),"r"(a[3]),"r"(b[0]),"r"(b[1]));
}
__device__ __forceinline__ uint32_t pack_hi(float2 v){
    __nv_bfloat162 h = __floats2bfloat162_rn(v.x, v.y);
    return *reinterpret_cast<uint32_t*>(&h);
}
__device__ __forceinline__ uint32_t pack_lo(float2 v, uint32_t hb){
    __nv_bfloat162 h = *reinterpret_cast<__nv_bfloat162*>(&hb);
    __nv_bfloat162 l = __floats2bfloat162_rn(v.x - __bfloat162float(h.x),
                                             v.y - __bfloat162float(h.y));
    return *reinterpret_cast<uint32_t*>(&l);
}

// ---------------- prep kernels ----------------
__global__ void prep_feat(const float* __restrict__ feat){
    int id = blockIdx.x*256 + threadIdx.x;
    if (id >= B_*HP*HP*C_) return;
    int c = id & 255; int rest = id >> 8;
    int xx = rest % HP; rest /= HP;
    int yy = rest % HP; int b = rest / HP;
    float v = 0.f;
    if (yy >= 1 && yy <= H_ && xx >= 1 && xx <= W_)
        v = feat[(((size_t)(b*C_ + c))*H_ + (yy-1))*W_ + (xx-1)];
    __nv_bfloat16 h = __float2bfloat16(v);
    g_Ah[id] = h;
    g_Al[id] = __float2bfloat16(v - __bfloat162float(h));
}

__global__ void prep_wconv(const float* __restrict__ cw, const float* __restrict__ cb,
                           const float* __restrict__ fw, const float* __restrict__ fb){
    int id = blockIdx.x*256 + threadIdx.x;
    if (id < 512) g_cbias[id] = (id < 256) ? cb[id] : fb[id-256];
    if (id >= 512*2304) return;
    int oc = id / 2304, k = id % 2304;
    int tap = k >> 8, ic = k & 255;
    float v = (oc < 256) ? cw[(oc*256 + ic)*9 + tap]
                         : fw[((oc-256)*256 + ic)*9 + tap];
    __nv_bfloat16 h = __float2bfloat16(v);
    g_Wth[id] = h;
    g_Wtl[id] = __float2bfloat16(v - __bfloat162float(h));
}

__global__ void prep_wmlp(const float* __restrict__ w0, const float* __restrict__ w1,
                          const float* __restrict__ w2){
    int id = blockIdx.x*256 + threadIdx.x;
    if (id >= 3*65536) return;
    int l = id >> 16, r = id & 65535;
    int n = r >> 8, k = r & 255;
    const float* w = (l==0) ? w0 : (l==1) ? w1 : w2;
    float v = w[k*256 + n];
    __nv_bfloat16 h = __float2bfloat16(v);
    g_Mth[id] = h;
    g_Mtl[id] = __float2bfloat16(v - __bfloat162float(h));
}

// ---------------- conv: dual 3x3 conv as implicit split-bf16 tensor GEMM ----------------
// block: 128 pixels (one image row) x 128 oc; K = 9*256 in steps of 32
#define CARR (128*40)       // bf16 elems per array per stage
#define CSTG (4*CARR)       // Ah,Al,Bh,Bl
__global__ __launch_bounds__(256) void conv_mma_kernel(){
    extern __shared__ __align__(16) __nv_bfloat16 cs[];   // [2][4][128*40]
    const int t = threadIdx.x, warp = t>>5, lane = t&31;
    const int oc0 = blockIdx.x*128, y = blockIdx.y, b = blockIdx.z;
    const int m0 = (warp>>2)*64, n0 = (warp&3)*32;

    float acc[4][4][4];
    #pragma unroll
    for (int i=0;i<4;++i)
        #pragma unroll
        for (int j=0;j<4;++j)
            #pragma unroll
            for (int q=0;q<4;++q) acc[i][j][q] = 0.f;

    auto issue = [&](int s, int stg){
        const int tap = s >> 3, sub = s & 7;
        const int ky = tap/3, kx = tap - ky*3;
        const int k0 = tap*256 + sub*32;
        __nv_bfloat16* dstb = cs + stg*CSTG;
        #pragma unroll
        for (int j=0;j<8;++j){
            int cid = t + j*256;
            int arr = cid >> 9, w = cid & 511, row = w >> 2, c = w & 3;
            uint32_t dst = smem_u32(dstb + arr*CARR + row*40 + c*8);
            const __nv_bfloat16* src;
            if (arr == 0)      src = g_Ah + ((size_t)((b*HP + y+ky)*HP + row+kx))*C_ + sub*32 + c*8;
            else if (arr == 1) src = g_Al + ((size_t)((b*HP + y+ky)*HP + row+kx))*C_ + sub*32 + c*8;
            else if (arr == 2) src = g_Wth + (size_t)(oc0+row)*2304 + k0 + c*8;
            else               src = g_Wtl + (size_t)(oc0+row)*2304 + k0 + c*8;
            cp16(dst, src);
        }
        cp_commit();
    };

    issue(0, 0);
    for (int s = 0; s < 72; ++s){
        const int stg = s & 1;
        if (s+1 < 72) issue(s+1, (s+1)&1);
        if (s+1 < 72) asm volatile("cp.async.wait_group 1;");
        else          asm volatile("cp.async.wait_group 0;");
        __syncthreads();
        const __nv_bfloat16* Ah = cs + stg*CSTG;
        const __nv_bfloat16* Al = Ah + CARR;
        const __nv_bfloat16* Bh = Al + CARR;
        const __nv_bfloat16* Bl = Bh + CARR;
        const int rsel = lane & 15, kgrp = (lane >> 4)*8;
        #pragma unroll
        for (int k16 = 0; k16 < 32; k16 += 16){
            uint32_t ah[4][4], al[4][4], bh[4][2], bl[4][2];
            #pragma unroll
            for (int mi=0;mi<4;++mi){
                uint32_t a0 = smem_u32(Ah + (m0+mi*16+rsel)*40 + k16 + kgrp);
                ldsm4(ah[mi][0],ah[mi][1],ah[mi][2],ah[mi][3], a0);
                uint32_t a1 = smem_u32(Al + (m0+mi*16+rsel)*40 + k16 + kgrp);
                ldsm4(al[mi][0],al[mi][1],al[mi][2],al[mi][3], a1);
            }
            #pragma unroll
            for (int nj=0;nj<2;++nj){
                uint32_t r0,r1,r2,r3;
                uint32_t a0 = smem_u32(Bh + (n0+nj*16+rsel)*40 + k16 + kgrp);
                ldsm4(r0,r1,r2,r3,a0);
                bh[2*nj][0]=r0; bh[2*nj][1]=r2; bh[2*nj+1][0]=r1; bh[2*nj+1][1]=r3;
                uint32_t a1 = smem_u32(Bl + (n0+nj*16+rsel)*40 + k16 + kgrp);
                ldsm4(r0,r1,r2,r3,a1);
                bl[2*nj][0]=r0; bl[2*nj][1]=r2; bl[2*nj+1][0]=r1; bl[2*nj+1][1]=r3;
            }
            #pragma unroll
            for (int mi=0;mi<4;++mi)
                #pragma unroll
                for (int ni=0;ni<4;++ni){
                    mma16816(acc[mi][ni], ah[mi], bh[ni]);
                    mma16816(acc[mi][ni], ah[mi], bl[ni]);
                    mma16816(acc[mi][ni], al[mi], bh[ni]);
                }
        }
        __syncthreads();
    }

    // epilogue: + bias, store fp32 pixel-major
    #pragma unroll
    for (int mi=0;mi<4;++mi){
        const int x = m0 + mi*16 + (lane>>2);
        #pragma unroll
        for (int ni=0;ni<4;++ni){
            const int col = oc0 + n0 + ni*8 + (lane&3)*2;
            float2 bb = *(const float2*)&g_cbias[col];
            float* o0 = g_cf + ((size_t)(b*HW_ + y*W_ + x))*512 + col;
            float* o1 = g_cf + ((size_t)(b*HW_ + y*W_ + x + 8))*512 + col;
            *(float2*)o0 = make_float2(acc[mi][ni][0]+bb.x, acc[mi][ni][1]+bb.y);
            *(float2*)o1 = make_float2(acc[mi][ni][2]+bb.x, acc[mi][ni][3]+bb.y);
        }
    }
}

// ---------------- point kernel: gather + sinusoid + split-bf16 tensor MLP ----------------
// block = 32 points x 4 shifts = 128 rows; 512 threads (16 warps)
// activations stored as bf16 hi/lo in smem (converted ONCE), A loaded via ldmatrix
#define MROWS 128
#define NPTS  32
#define XP    264                 // bf16 pitch for X rows (528B: conflict-free ldmatrix)
#define WP    24                  // bf16 pitch for 16-k weight chunk rows
#define WARRp (256*WP)            // bf16 elems per comp per stage
#define WSTGp (2*WARRp)           // hi + lo
__global__ __launch_bounds__(512) void point_mma_kernel(
        const float* __restrict__ pc,
        const float* __restrict__ phase_w,
        const float* __restrict__ b0, const float* __restrict__ b1,
        const float* __restrict__ b2,
        const float* __restrict__ w3, const float* __restrict__ b3,
        const float* __restrict__ coarse,
        float* __restrict__ out) {
    extern __shared__ __align__(16) __nv_bfloat16 smb[];
    __nv_bfloat16* Xh = smb;                         // 128*264
    __nv_bfloat16* Xl = Xh + MROWS*XP;               // 128*264
    __nv_bfloat16* Wt = Xl + MROWS*XP;               // 2 stages * WSTGp
    float* misc  = (float*)(Wt + 2*WSTGp);
    float* ph     = misc;                  // 256
    float* s_rel0 = ph + 256;              // 128
    float* s_rel1 = s_rel0 + 128;          // 128
    float* s_area = s_rel1 + 128;          // 128
    int*   s_pix  = (int*)(s_area + 128);  // 128
    int*   s_phof = s_pix + 128;           // 128
    float* w3s    = (float*)(s_phof + 128);// 514
    float* s_pr   = w3s + 514;             // 256

    const int t = threadIdx.x, warp = t>>5, lane = t&31;
    const int g0 = blockIdx.x * NPTS;
    const int m0 = (warp>>2)*32, n0 = (warp&3)*64;
    const int rsel = lane & 15, kgrp = (lane >> 4)*8;

    // constants into smem
    if (t < 128) {
        float p0 = phase_w[2*t], p1 = phase_w[2*t+1];
        ph[t]       = fmaf(8.f,   p0, 8.f*p1);
        ph[128 + t] = fmaf(128.f, p0, 128.f*p1);
    }
    for (int i = t; i < 514; i += 512)
        w3s[i] = (i < 512) ? w3[i] : b3[i - 512];

    // stage 1: per-row pixel index / rel / area
    if (t < MROWS) {
        const int p_local = t >> 2, s = t & 3;
        const int g = g0 + p_local;
        const int q = g & (Q_ - 1);
        const float pc0 = pc[2*g], pc1 = pc[2*g + 1];
        const float SH_P = (float)( 1.0/128.0 + 1e-6);
        const float SH_M = (float)(-1.0/128.0 + 1e-6);
        const float LO = (float)(-1.0 + 1e-6), HI = (float)(1.0 - 1e-6);
        float cy = pc0 + ((s >= 2) ? SH_P : SH_M);
        float cx = pc1 + ((s & 1) ? SH_P : SH_M);
        cy = fminf(fmaxf(cy, LO), HI);
        cx = fminf(fmaxf(cx, LO), HI);
        int iy = (int)rintf(((cy + 1.f)*128.f - 1.f)*0.5f);
        int ix = (int)rintf(((cx + 1.f)*128.f - 1.f)*0.5f);
        iy = min(max(iy, 0), 127); ix = min(max(ix, 0), 127);
        float qcy = -0.9921875f + 0.015625f*(float)iy;
        float qcx = -0.9921875f + 0.015625f*(float)ix;
        float rel0 = (pc0 - qcy)*128.f;
        float rel1 = (pc1 - qcx)*128.f;
        s_pix[t]  = iy*W_ + ix;
        s_rel0[t] = rel0;  s_rel1[t] = rel1;
        s_area[t] = fabsf(rel0*rel1) + 1e-9f;
        s_phof[t] = (q < 2) ? 0 : 128;
    }
    __syncthreads();

    // weight prefetch: 48 chunks of k=16 (3 layers x 16)
    auto wissue = [&](int g, int stg){
        const int L = g >> 4, s = g & 15;
        __nv_bfloat16* dstb = Wt + stg*WSTGp;
        const __nv_bfloat16* srch = g_Mth + L*65536;
        const __nv_bfloat16* srcl = g_Mtl + L*65536;
        #pragma unroll
        for (int j=0;j<2;++j){
            int cid = t + j*512;
            int comp = cid >> 9, w = cid & 511, row = w >> 1, c = w & 1;
            uint32_t dst = smem_u32(dstb + comp*WARRp + row*WP + c*8);
            const __nv_bfloat16* src = (comp ? srcl : srch) + row*256 + s*16 + c*8;
            cp16(dst, src);
        }
        cp_commit();
    };
    wissue(0, 0);

    // stage 2: gather + sinusoidal features -> Xh/Xl (bf16 hi/lo, converted once)
    {
        #pragma unroll 1
        for (int rr = 0; rr < 8; ++rr) {
            const int r = warp*8 + rr;
            const int g = g0 + (r >> 2);
            const int bb = g >> 15;
            const float* base = g_cf + ((size_t)(bb*HW_ + s_pix[r])) * 512;
            const float rel0 = s_rel0[r], rel1 = s_rel1[r];
            const float* php = ph + s_phof[r];
            #pragma unroll
            for (int i = 0; i < 2; ++i) {
                const int kp = lane + 32*i;       // pair index 0..63
                const int k0 = 2*kp;              // k in 0..126 even
                float4 f4 = *(const float4*)(base + 256 + 2*k0);   // freq pairs
                float2 cc = *(const float2*)(base + k0);            // coef (cos half)
                float2 cs2 = *(const float2*)(base + 128 + k0);     // coef (sin half)
                float2 ph2 = *(const float2*)(php + k0);
                float qf0 = fmaf(f4.x, rel0, fmaf(f4.y, rel1, ph2.x));
                float qf1 = fmaf(f4.z, rel0, fmaf(f4.w, rel1, ph2.y));
                float sv0, cv0, sv1, cv1;
                sincospif(qf0, &sv0, &cv0);
                sincospif(qf1, &sv1, &cv1);
                float2 vc = make_float2(cc.x*cv0,  cc.y*cv1);
                float2 vs = make_float2(cs2.x*sv0, cs2.y*sv1);
                uint32_t hc = pack_hi(vc), hs = pack_hi(vs);
                *(uint32_t*)&Xh[r*XP + k0]       = hc;
                *(uint32_t*)&Xl[r*XP + k0]       = pack_lo(vc, hc);
                *(uint32_t*)&Xh[r*XP + 128 + k0] = hs;
                *(uint32_t*)&Xl[r*XP + 128 + k0] = pack_lo(vs, hs);
            }
        }
    }

    // stage 3: 3 layers of split-bf16 tensor GEMM, K chunks of 16
    float acc[2][8][4];
    for (int g = 0; g < 48; ++g){
        const int L = g >> 4, s = g & 15, stg = g & 1;
        if (s == 0){
            #pragma unroll
            for (int i=0;i<2;++i)
                #pragma unroll
                for (int j=0;j<8;++j)
                    #pragma unroll
                    for (int q=0;q<4;++q) acc[i][j][q] = 0.f;
        }
        if (g+1 < 48) wissue(g+1, (g+1)&1);
        if (g+1 < 48) asm volatile("cp.async.wait_group 1;");
        else          asm volatile("cp.async.wait_group 0;");
        __syncthreads();

        const __nv_bfloat16* WH = Wt + stg*WSTGp;
        const __nv_bfloat16* WL = WH + WARRp;
        const int k0 = s*16;

        uint32_t AH[2][4], AL[2][4];
        #pragma unroll
        for (int mi=0;mi<2;++mi){
            ldsm4(AH[mi][0],AH[mi][1],AH[mi][2],AH[mi][3],
                  smem_u32(Xh + (m0+mi*16+rsel)*XP + k0 + kgrp));
            ldsm4(AL[mi][0],AL[mi][1],AL[mi][2],AL[mi][3],
                  smem_u32(Xl + (m0+mi*16+rsel)*XP + k0 + kgrp));
        }
        #pragma unroll
        for (int nj=0;nj<4;++nj){
            uint32_t r0,r1,r2,r3, q0,q1,q2,q3;
            ldsm4(r0,r1,r2,r3, smem_u32(WH + (n0+nj*16+rsel)*WP + kgrp));
            ldsm4(q0,q1,q2,q3, smem_u32(WL + (n0+nj*16+rsel)*WP + kgrp));
            uint32_t bh0[2] = {r0, r2}, bh1[2] = {r1, r3};
            uint32_t bl0[2] = {q0, q2}, bl1[2] = {q1, q3};
            #pragma unroll
            for (int mi=0;mi<2;++mi){
                mma16816(acc[mi][2*nj],   AH[mi], bh0);
                mma16816(acc[mi][2*nj],   AH[mi], bl0);
                mma16816(acc[mi][2*nj],   AL[mi], bh0);
                mma16816(acc[mi][2*nj+1], AH[mi], bh1);
                mma16816(acc[mi][2*nj+1], AH[mi], bl1);
                mma16816(acc[mi][2*nj+1], AL[mi], bh1);
            }
        }
        __syncthreads();

        if (s == 15){
            // layer epilogue: relu(acc + bias) -> Xh/Xl in place (bf16 hi/lo, once)
            const float* bg = (L==0) ? b0 : (L==1) ? b1 : b2;
            #pragma unroll
            for (int mi=0;mi<2;++mi){
                const int r = m0 + mi*16 + (lane>>2);
                #pragma unroll
                for (int ni=0;ni<8;++ni){
                    const int c = n0 + ni*8 + (lane&3)*2;
                    float2 bb = *(const float2*)&bg[c];
                    float2 v0 = make_float2(fmaxf(acc[mi][ni][0]+bb.x, 0.f),
                                            fmaxf(acc[mi][ni][1]+bb.y, 0.f));
                    float2 v1 = make_float2(fmaxf(acc[mi][ni][2]+bb.x, 0.f),
                                            fmaxf(acc[mi][ni][3]+bb.y, 0.f));
                    uint32_t h0 = pack_hi(v0), h1 = pack_hi(v1);
                    *(uint32_t*)&Xh[r*XP + c]     = h0;
                    *(uint32_t*)&Xl[r*XP + c]     = pack_lo(v0, h0);
                    *(uint32_t*)&Xh[(r+8)*XP + c] = h1;
                    *(uint32_t*)&Xl[(r+8)*XP + c] = pack_lo(v1, h1);
                }
            }
            __syncthreads();
        }
    }

    // final 256->2 layer (fp32, reconstruct x = hi + lo)
    if (t < 2*MROWS) {
        const int r = t >> 1, c = t & 1;
        const __nv_bfloat16* rh = Xh + r*XP;
        const __nv_bfloat16* rl = Xl + r*XP;
        float sum = w3s[512 + c];
        #pragma unroll 4
        for (int i = 0; i < 128; ++i) {
            uint32_t hu = *(const uint32_t*)&rh[2*i];
            uint32_t lu = *(const uint32_t*)&rl[2*i];
            __nv_bfloat162 hb = *reinterpret_cast<__nv_bfloat162*>(&hu);
            __nv_bfloat162 lb = *reinterpret_cast<__nv_bfloat162*>(&lu);
            float x0 = __bfloat162float(hb.x) + __bfloat162float(lb.x);
            float x1 = __bfloat162float(hb.y) + __bfloat162float(lb.y);
            sum = fmaf(x0, w3s[4*i + c], sum);
            sum = fmaf(x1, w3s[4*i + 2 + c], sum);
        }
        s_pr[2*r + c] = sum;
    }
    __syncthreads();

    // local-ensemble combine + coarse residual
    if (t < 2*NPTS) {
        const int p = t >> 1, c = t & 1;
        const int rb = p*4;
        float a0 = s_area[rb+0], a1 = s_area[rb+1], a2 = s_area[rb+2], a3 = s_area[rb+3];
        float tot = a0 + a1 + a2 + a3;
        float v = s_pr[2*(rb+0)+c]*a3 + s_pr[2*(rb+1)+c]*a2
                + s_pr[2*(rb+2)+c]*a1 + s_pr[2*(rb+3)+c]*a0;
        v /= tot;
        const int g = g0 + p;
        const int bb = g >> 15, q = g & (Q_ - 1);
        const int oidx = (bb*2 + c)*Q_ + q;
        out[oidx] = v + coarse[oidx];
    }
}

// ---------------- launch ----------------
extern "C" void kernel_launch(void* const* d_in, const int* in_sizes, int n_in,
                              void* d_out, int out_size) {
    const float* feat    = (const float*)d_in[0];
    const float* pcoords = (const float*)d_in[1];
    const float* coarse  = (const float*)d_in[2];
    const float* coef_w  = (const float*)d_in[4];
    const float* coef_b  = (const float*)d_in[5];
    const float* freq_w  = (const float*)d_in[6];
    const float* freq_b  = (const float*)d_in[7];
    const float* phase_w = (const float*)d_in[8];
    const float* b0 = (const float*)d_in[10];
    const float* b1 = (const float*)d_in[12];
    const float* b2 = (const float*)d_in[14];
    const float* w3 = (const float*)d_in[15];
    const float* b3 = (const float*)d_in[16];
    float* out = (float*)d_out;

    prep_feat<<<(B_*HP*HP*C_ + 255)/256, 256>>>(feat);
    prep_wconv<<<(512*2304 + 255)/256, 256>>>(coef_w, coef_b, freq_w, freq_b);
    prep_wmlp<<<(3*65536 + 255)/256, 256>>>((const float*)d_in[9], (const float*)d_in[11],
                                            (const float*)d_in[13]);

    const int CSMEM = 2*CSTG*2;  // 81920 B
    cudaFuncSetAttribute(conv_mma_kernel, cudaFuncAttributeMaxDynamicSharedMemorySize, CSMEM);
    conv_mma_kernel<<<dim3(4, 128, 2), 256, CSMEM>>>();

    // point kernel smem: Xh + Xl + weights(2 stages) + misc
    const int PSMEM = (MROWS*XP*2)*2 + (2*WSTGp)*2
                    + (256 + 128*3 + 514 + 256)*4 + 128*2*4 + 64;
    cudaFuncSetAttribute(point_mma_kernel, cudaFuncAttributeMaxDynamicSharedMemorySize, PSMEM);
    point_mma_kernel<<<(B_*Q_)/NPTS, 512, PSMEM>>>(pcoords, phase_w,
                                                   b0, b1, b2, w3, b3,
                                                   coarse, out);
}

// round 6
// speedup vs baseline: 3.3105x; 1.3585x over previous
#include <cuda_runtime.h>
#include <cuda_bf16.h>
#include <cuda_fp16.h>
#include <cstdint>
#include <cstddef>

#define B_ 2
#define C_ 256
#define H_ 128
#define W_ 128
#define Q_ 32768
#define HP 130
#define HW_ (H_*W_)

// ---------------- static device scratch ----------------
__device__ __align__(16) __nv_bfloat16 g_Ah[(size_t)B_*HP*HP*C_];   // padded NHWC hi
__device__ __align__(16) __nv_bfloat16 g_Al[(size_t)B_*HP*HP*C_];   // padded NHWC lo
__device__ __align__(16) __nv_bfloat16 g_Wth[512*2304];             // conv W^T [oc][k] hi
__device__ __align__(16) __nv_bfloat16 g_Wtl[512*2304];             // lo
__device__ __align__(16) __half        g_Mh[3*256*256];             // mlp W^T [l][n][k] fp16 (hi only)
__device__ float g_cbias[512];
__device__ __align__(16) float g_cf[(size_t)B_*HW_*512];            // conv out [b][pix][512] fp32

// ---------------- helpers ----------------
__device__ __forceinline__ uint32_t smem_u32(const void* p){
    return (uint32_t)__cvta_generic_to_shared(p);
}
__device__ __forceinline__ void ldsm4(uint32_t& r0,uint32_t& r1,uint32_t& r2,uint32_t& r3,uint32_t a){
    asm volatile("ldmatrix.sync.aligned.m8n8.x4.shared.b16 {%0,%1,%2,%3},[%4];"
        :"=r"(r0),"=r"(r1),"=r"(r2),"=r"(r3):"r"(a));
}
__device__ __forceinline__ void cp16(uint32_t d, const void* s){
    asm volatile("cp.async.ca.shared.global [%0],[%1],16;"::"r"(d),"l"(s));
}
__device__ __forceinline__ void cp_commit(){ asm volatile("cp.async.commit_group;"); }
// bf16 mma (conv)
__device__ __forceinline__ void mma16816(float* c, const uint32_t* a, const uint32_t* b){
    asm volatile("mma.sync.aligned.m16n8k16.row.col.f32.bf16.bf16.f32 "
        "{%0,%1,%2,%3},{%4,%5,%6,%7},{%8,%9},{%0,%1,%2,%3};"
        : "+f"(c[0]),"+f"(c[1]),"+f"(c[2]),"+f"(c[3])
        : "r"(a[0]),"r"(a[1]),"r"(a[2]),"r"(a[3]),"r"(b[0]),"r"(b[1]));
}
// fp16 mma (MLP)
__device__ __forceinline__ void mma16816h(float* c, const uint32_t* a, const uint32_t* b){
    asm volatile("mma.sync.aligned.m16n8k16.row.col.f32.f16.f16.f32 "
        "{%0,%1,%2,%3},{%4,%5,%6,%7},{%8,%9},{%0,%1,%2,%3};"
        : "+f"(c[0]),"+f"(c[1]),"+f"(c[2]),"+f"(c[3])
        : "r"(a[0]),"r"(a[1]),"r"(a[2]),"r"(a[3]),"r"(b[0]),"r"(b[1]));
}
__device__ __forceinline__ uint32_t pack_hi(float2 v){
    __nv_bfloat162 h = __floats2bfloat162_rn(v.x, v.y);
    return *reinterpret_cast<uint32_t*>(&h);
}
__device__ __forceinline__ uint32_t pack_lo(float2 v, uint32_t hb){
    __nv_bfloat162 h = *reinterpret_cast<__nv_bfloat162*>(&hb);
    __nv_bfloat162 l = __floats2bfloat162_rn(v.x - __bfloat162float(h.x),
                                             v.y - __bfloat162float(h.y));
    return *reinterpret_cast<uint32_t*>(&l);
}
__device__ __forceinline__ uint32_t pack_hi16(float2 v){
    __half2 h = __floats2half2_rn(v.x, v.y);
    return *reinterpret_cast<uint32_t*>(&h);
}
__device__ __forceinline__ uint32_t pack_lo16(float2 v, uint32_t hb){
    __half2 h = *reinterpret_cast<__half2*>(&hb);
    __half2 l = __floats2half2_rn(v.x - __half2float(h.x),
                                  v.y - __half2float(h.y));
    return *reinterpret_cast<uint32_t*>(&l);
}

// ---------------- prep kernels ----------------
__global__ void prep_feat(const float* __restrict__ feat){
    int id = blockIdx.x*256 + threadIdx.x;
    if (id >= B_*HP*HP*C_) return;
    int c = id & 255; int rest = id >> 8;
    int xx = rest % HP; rest /= HP;
    int yy = rest % HP; int b = rest / HP;
    float v = 0.f;
    if (yy >= 1 && yy <= H_ && xx >= 1 && xx <= W_)
        v = feat[(((size_t)(b*C_ + c))*H_ + (yy-1))*W_ + (xx-1)];
    __nv_bfloat16 h = __float2bfloat16(v);
    g_Ah[id] = h;
    g_Al[id] = __float2bfloat16(v - __bfloat162float(h));
}

__global__ void prep_wconv(const float* __restrict__ cw, const float* __restrict__ cb,
                           const float* __restrict__ fw, const float* __restrict__ fb){
    int id = blockIdx.x*256 + threadIdx.x;
    if (id < 512) g_cbias[id] = (id < 256) ? cb[id] : fb[id-256];
    if (id >= 512*2304) return;
    int oc = id / 2304, k = id % 2304;
    int tap = k >> 8, ic = k & 255;
    float v = (oc < 256) ? cw[(oc*256 + ic)*9 + tap]
                         : fw[((oc-256)*256 + ic)*9 + tap];
    __nv_bfloat16 h = __float2bfloat16(v);
    g_Wth[id] = h;
    g_Wtl[id] = __float2bfloat16(v - __bfloat162float(h));
}

__global__ void prep_wmlp(const float* __restrict__ w0, const float* __restrict__ w1,
                          const float* __restrict__ w2){
    int id = blockIdx.x*256 + threadIdx.x;
    if (id >= 3*65536) return;
    int l = id >> 16, r = id & 65535;
    int n = r >> 8, k = r & 255;
    const float* w = (l==0) ? w0 : (l==1) ? w1 : w2;
    g_Mh[id] = __float2half_rn(w[k*256 + n]);
}

// ---------------- conv: dual 3x3 conv as implicit split-bf16 tensor GEMM ----------------
// block: 128 pixels (one image row) x 128 oc; K = 9*256 in steps of 32
#define CARR (128*40)
#define CSTG (4*CARR)
__global__ __launch_bounds__(256) void conv_mma_kernel(){
    extern __shared__ __align__(16) __nv_bfloat16 cs[];
    const int t = threadIdx.x, warp = t>>5, lane = t&31;
    const int oc0 = blockIdx.x*128, y = blockIdx.y, b = blockIdx.z;
    const int m0 = (warp>>2)*64, n0 = (warp&3)*32;

    float acc[4][4][4];
    #pragma unroll
    for (int i=0;i<4;++i)
        #pragma unroll
        for (int j=0;j<4;++j)
            #pragma unroll
            for (int q=0;q<4;++q) acc[i][j][q] = 0.f;

    auto issue = [&](int s, int stg){
        const int tap = s >> 3, sub = s & 7;
        const int ky = tap/3, kx = tap - ky*3;
        const int k0 = tap*256 + sub*32;
        __nv_bfloat16* dstb = cs + stg*CSTG;
        #pragma unroll
        for (int j=0;j<8;++j){
            int cid = t + j*256;
            int arr = cid >> 9, w = cid & 511, row = w >> 2, c = w & 3;
            uint32_t dst = smem_u32(dstb + arr*CARR + row*40 + c*8);
            const __nv_bfloat16* src;
            if (arr == 0)      src = g_Ah + ((size_t)((b*HP + y+ky)*HP + row+kx))*C_ + sub*32 + c*8;
            else if (arr == 1) src = g_Al + ((size_t)((b*HP + y+ky)*HP + row+kx))*C_ + sub*32 + c*8;
            else if (arr == 2) src = g_Wth + (size_t)(oc0+row)*2304 + k0 + c*8;
            else               src = g_Wtl + (size_t)(oc0+row)*2304 + k0 + c*8;
            cp16(dst, src);
        }
        cp_commit();
    };

    issue(0, 0);
    for (int s = 0; s < 72; ++s){
        const int stg = s & 1;
        if (s+1 < 72) issue(s+1, (s+1)&1);
        if (s+1 < 72) asm volatile("cp.async.wait_group 1;");
        else          asm volatile("cp.async.wait_group 0;");
        __syncthreads();
        const __nv_bfloat16* Ah = cs + stg*CSTG;
        const __nv_bfloat16* Al = Ah + CARR;
        const __nv_bfloat16* Bh = Al + CARR;
        const __nv_bfloat16* Bl = Bh + CARR;
        const int rsel = lane & 15, kgrp = (lane >> 4)*8;
        #pragma unroll
        for (int k16 = 0; k16 < 32; k16 += 16){
            uint32_t ah[4][4], al[4][4], bh[4][2], bl[4][2];
            #pragma unroll
            for (int mi=0;mi<4;++mi){
                uint32_t a0 = smem_u32(Ah + (m0+mi*16+rsel)*40 + k16 + kgrp);
                ldsm4(ah[mi][0],ah[mi][1],ah[mi][2],ah[mi][3], a0);
                uint32_t a1 = smem_u32(Al + (m0+mi*16+rsel)*40 + k16 + kgrp);
                ldsm4(al[mi][0],al[mi][1],al[mi][2],al[mi][3], a1);
            }
            #pragma unroll
            for (int nj=0;nj<2;++nj){
                uint32_t r0,r1,r2,r3;
                uint32_t a0 = smem_u32(Bh + (n0+nj*16+rsel)*40 + k16 + kgrp);
                ldsm4(r0,r1,r2,r3,a0);
                bh[2*nj][0]=r0; bh[2*nj][1]=r2; bh[2*nj+1][0]=r1; bh[2*nj+1][1]=r3;
                uint32_t a1 = smem_u32(Bl + (n0+nj*16+rsel)*40 + k16 + kgrp);
                ldsm4(r0,r1,r2,r3,a1);
                bl[2*nj][0]=r0; bl[2*nj][1]=r2; bl[2*nj+1][0]=r1; bl[2*nj+1][1]=r3;
            }
            #pragma unroll
            for (int mi=0;mi<4;++mi)
                #pragma unroll
                for (int ni=0;ni<4;++ni){
                    mma16816(acc[mi][ni], ah[mi], bh[ni]);
                    mma16816(acc[mi][ni], ah[mi], bl[ni]);
                    mma16816(acc[mi][ni], al[mi], bh[ni]);
                }
        }
        __syncthreads();
    }

    #pragma unroll
    for (int mi=0;mi<4;++mi){
        const int x = m0 + mi*16 + (lane>>2);
        #pragma unroll
        for (int ni=0;ni<4;++ni){
            const int col = oc0 + n0 + ni*8 + (lane&3)*2;
            float2 bb = *(const float2*)&g_cbias[col];
            float* o0 = g_cf + ((size_t)(b*HW_ + y*W_ + x))*512 + col;
            float* o1 = g_cf + ((size_t)(b*HW_ + y*W_ + x + 8))*512 + col;
            *(float2*)o0 = make_float2(acc[mi][ni][0]+bb.x, acc[mi][ni][1]+bb.y);
            *(float2*)o1 = make_float2(acc[mi][ni][2]+bb.x, acc[mi][ni][3]+bb.y);
        }
    }
}

// ---------------- point kernel: gather + sinusoid + fp16 2-term tensor MLP ----------------
// block = 32 points x 4 shifts = 128 rows; 512 threads (16 warps)
// activations fp16 hi/lo in smem; weights fp16 hi-only (k-chunks of 32, double-buffered)
#define MROWS 128
#define NPTS  32
#define XP    264                 // fp16 pitch for X rows (528B: conflict-free ldmatrix)
#define WP    40                  // fp16 pitch for 32-k weight chunk rows
#define WSTG  (256*WP)            // fp16 elems per stage
__global__ __launch_bounds__(512) void point_mma_kernel(
        const float* __restrict__ pc,
        const float* __restrict__ phase_w,
        const float* __restrict__ b0, const float* __restrict__ b1,
        const float* __restrict__ b2,
        const float* __restrict__ w3, const float* __restrict__ b3,
        const float* __restrict__ coarse,
        float* __restrict__ out) {
    extern __shared__ __align__(16) __half smh[];
    __half* Xh = smh;                          // 128*264
    __half* Xl = Xh + MROWS*XP;                // 128*264
    __half* Wt = Xl + MROWS*XP;                // 2 stages * WSTG
    float* misc  = (float*)(Wt + 2*WSTG);
    float* ph     = misc;                  // 256
    float* s_rel0 = ph + 256;              // 128
    float* s_rel1 = s_rel0 + 128;          // 128
    float* s_area = s_rel1 + 128;          // 128
    int*   s_pix  = (int*)(s_area + 128);  // 128
    int*   s_phof = s_pix + 128;           // 128
    float* w3s    = (float*)(s_phof + 128);// 514
    float* s_pr   = w3s + 514;             // 256

    const int t = threadIdx.x, warp = t>>5, lane = t&31;
    const int g0 = blockIdx.x * NPTS;
    const int m0 = (warp>>2)*32, n0 = (warp&3)*64;
    const int rsel = lane & 15, kgrp = (lane >> 4)*8;

    // constants into smem
    if (t < 128) {
        float p0 = phase_w[2*t], p1 = phase_w[2*t+1];
        ph[t]       = fmaf(8.f,   p0, 8.f*p1);
        ph[128 + t] = fmaf(128.f, p0, 128.f*p1);
    }
    for (int i = t; i < 514; i += 512)
        w3s[i] = (i < 512) ? w3[i] : b3[i - 512];

    // stage 1: per-row pixel index / rel / area
    if (t < MROWS) {
        const int p_local = t >> 2, s = t & 3;
        const int g = g0 + p_local;
        const int q = g & (Q_ - 1);
        const float pc0 = pc[2*g], pc1 = pc[2*g + 1];
        const float SH_P = (float)( 1.0/128.0 + 1e-6);
        const float SH_M = (float)(-1.0/128.0 + 1e-6);
        const float LO = (float)(-1.0 + 1e-6), HI = (float)(1.0 - 1e-6);
        float cy = pc0 + ((s >= 2) ? SH_P : SH_M);
        float cx = pc1 + ((s & 1) ? SH_P : SH_M);
        cy = fminf(fmaxf(cy, LO), HI);
        cx = fminf(fmaxf(cx, LO), HI);
        int iy = (int)rintf(((cy + 1.f)*128.f - 1.f)*0.5f);
        int ix = (int)rintf(((cx + 1.f)*128.f - 1.f)*0.5f);
        iy = min(max(iy, 0), 127); ix = min(max(ix, 0), 127);
        float qcy = -0.9921875f + 0.015625f*(float)iy;
        float qcx = -0.9921875f + 0.015625f*(float)ix;
        float rel0 = (pc0 - qcy)*128.f;
        float rel1 = (pc1 - qcx)*128.f;
        s_pix[t]  = iy*W_ + ix;
        s_rel0[t] = rel0;  s_rel1[t] = rel1;
        s_area[t] = fabsf(rel0*rel1) + 1e-9f;
        s_phof[t] = (q < 2) ? 0 : 128;
    }
    __syncthreads();

    // weight prefetch: 24 chunks of k=32 (3 layers x 8), fp16 hi only
    auto wissue = [&](int g, int stg){
        const int L = g >> 3, s = g & 7;
        __half* dstb = Wt + stg*WSTG;
        const __half* srcb = g_Mh + L*65536 + s*32;
        #pragma unroll
        for (int j=0;j<2;++j){
            int cid = t + j*512;            // 0..1023
            int n = cid >> 2, c = cid & 3;
            uint32_t dst = smem_u32(dstb + n*WP + c*8);
            cp16(dst, srcb + n*256 + c*8);
        }
        cp_commit();
    };
    wissue(0, 0);

    // stage 2: gather + sinusoidal features -> Xh/Xl (fp16 hi/lo)
    {
        #pragma unroll 1
        for (int rr = 0; rr < 8; ++rr) {
            const int r = warp*8 + rr;
            const int g = g0 + (r >> 2);
            const int bb = g >> 15;
            const float* base = g_cf + ((size_t)(bb*HW_ + s_pix[r])) * 512;
            const float rel0 = s_rel0[r], rel1 = s_rel1[r];
            const float* php = ph + s_phof[r];
            #pragma unroll
            for (int i = 0; i < 2; ++i) {
                const int kp = lane + 32*i;       // pair index 0..63
                const int k0 = 2*kp;              // k in 0..126 even
                float4 f4 = *(const float4*)(base + 256 + 2*k0);   // freq pairs
                float2 cc = *(const float2*)(base + k0);            // coef (cos half)
                float2 cs2 = *(const float2*)(base + 128 + k0);     // coef (sin half)
                float2 ph2 = *(const float2*)(php + k0);
                float qf0 = fmaf(f4.x, rel0, fmaf(f4.y, rel1, ph2.x));
                float qf1 = fmaf(f4.z, rel0, fmaf(f4.w, rel1, ph2.y));
                float sv0, cv0, sv1, cv1;
                sincospif(qf0, &sv0, &cv0);
                sincospif(qf1, &sv1, &cv1);
                float2 vc = make_float2(cc.x*cv0,  cc.y*cv1);
                float2 vs = make_float2(cs2.x*sv0, cs2.y*sv1);
                uint32_t hc = pack_hi16(vc), hs = pack_hi16(vs);
                *(uint32_t*)&Xh[r*XP + k0]       = hc;
                *(uint32_t*)&Xl[r*XP + k0]       = pack_lo16(vc, hc);
                *(uint32_t*)&Xh[r*XP + 128 + k0] = hs;
                *(uint32_t*)&Xl[r*XP + 128 + k0] = pack_lo16(vs, hs);
            }
        }
    }

    // stage 3: 3 layers of fp16 2-term tensor GEMM, K chunks of 32
    float acc[2][8][4];
    for (int g = 0; g < 24; ++g){
        const int L = g >> 3, kc = g & 7, stg = g & 1;
        if (kc == 0){
            #pragma unroll
            for (int i=0;i<2;++i)
                #pragma unroll
                for (int j=0;j<8;++j)
                    #pragma unroll
                    for (int q=0;q<4;++q) acc[i][j][q] = 0.f;
        }
        if (g+1 < 24) wissue(g+1, (g+1)&1);
        if (g+1 < 24) asm volatile("cp.async.wait_group 1;");
        else          asm volatile("cp.async.wait_group 0;");
        __syncthreads();

        const __half* WH = Wt + stg*WSTG;
        #pragma unroll
        for (int kh = 0; kh < 2; ++kh){
            const int k16 = kc*32 + kh*16;
            uint32_t AH[2][4], AL[2][4];
            #pragma unroll
            for (int mi=0;mi<2;++mi){
                ldsm4(AH[mi][0],AH[mi][1],AH[mi][2],AH[mi][3],
                      smem_u32(Xh + (m0+mi*16+rsel)*XP + k16 + kgrp));
                ldsm4(AL[mi][0],AL[mi][1],AL[mi][2],AL[mi][3],
                      smem_u32(Xl + (m0+mi*16+rsel)*XP + k16 + kgrp));
            }
            #pragma unroll
            for (int nj=0;nj<4;++nj){
                uint32_t r0,r1,r2,r3;
                ldsm4(r0,r1,r2,r3, smem_u32(WH + (n0+nj*16+rsel)*WP + kh*16 + kgrp));
                uint32_t b0r[2] = {r0, r2}, b1r[2] = {r1, r3};
                #pragma unroll
                for (int mi=0;mi<2;++mi){
                    mma16816h(acc[mi][2*nj],   AH[mi], b0r);
                    mma16816h(acc[mi][2*nj],   AL[mi], b0r);
                    mma16816h(acc[mi][2*nj+1], AH[mi], b1r);
                    mma16816h(acc[mi][2*nj+1], AL[mi], b1r);
                }
            }
        }
        __syncthreads();

        if (kc == 7){
            // layer epilogue: relu(acc + bias) -> Xh/Xl in place (fp16 hi/lo)
            const float* bg = (L==0) ? b0 : (L==1) ? b1 : b2;
            #pragma unroll
            for (int mi=0;mi<2;++mi){
                const int r = m0 + mi*16 + (lane>>2);
                #pragma unroll
                for (int ni=0;ni<8;++ni){
                    const int c = n0 + ni*8 + (lane&3)*2;
                    float2 bb = *(const float2*)&bg[c];
                    float2 v0 = make_float2(fmaxf(acc[mi][ni][0]+bb.x, 0.f),
                                            fmaxf(acc[mi][ni][1]+bb.y, 0.f));
                    float2 v1 = make_float2(fmaxf(acc[mi][ni][2]+bb.x, 0.f),
                                            fmaxf(acc[mi][ni][3]+bb.y, 0.f));
                    uint32_t h0 = pack_hi16(v0), h1 = pack_hi16(v1);
                    *(uint32_t*)&Xh[r*XP + c]     = h0;
                    *(uint32_t*)&Xl[r*XP + c]     = pack_lo16(v0, h0);
                    *(uint32_t*)&Xh[(r+8)*XP + c] = h1;
                    *(uint32_t*)&Xl[(r+8)*XP + c] = pack_lo16(v1, h1);
                }
            }
            __syncthreads();
        }
    }

    // final 256->2 layer (fp32, reconstruct x = hi + lo)
    if (t < 2*MROWS) {
        const int r = t >> 1, c = t & 1;
        const __half* rh = Xh + r*XP;
        const __half* rl = Xl + r*XP;
        float sum = w3s[512 + c];
        #pragma unroll 4
        for (int i = 0; i < 128; ++i) {
            uint32_t hu = *(const uint32_t*)&rh[2*i];
            uint32_t lu = *(const uint32_t*)&rl[2*i];
            __half2 hb = *reinterpret_cast<__half2*>(&hu);
            __half2 lb = *reinterpret_cast<__half2*>(&lu);
            float x0 = __half2float(hb.x) + __half2float(lb.x);
            float x1 = __half2float(hb.y) + __half2float(lb.y);
            sum = fmaf(x0, w3s[4*i + c], sum);
            sum = fmaf(x1, w3s[4*i + 2 + c], sum);
        }
        s_pr[2*r + c] = sum;
    }
    __syncthreads();

    // local-ensemble combine + coarse residual
    if (t < 2*NPTS) {
        const int p = t >> 1, c = t & 1;
        const int rb = p*4;
        float a0 = s_area[rb+0], a1 = s_area[rb+1], a2 = s_area[rb+2], a3 = s_area[rb+3];
        float tot = a0 + a1 + a2 + a3;
        float v = s_pr[2*(rb+0)+c]*a3 + s_pr[2*(rb+1)+c]*a2
                + s_pr[2*(rb+2)+c]*a1 + s_pr[2*(rb+3)+c]*a0;
        v /= tot;
        const int g = g0 + p;
        const int bb = g >> 15, q = g & (Q_ - 1);
        const int oidx = (bb*2 + c)*Q_ + q;
        out[oidx] = v + coarse[oidx];
    }
}

// ---------------- launch ----------------
extern "C" void kernel_launch(void* const* d_in, const int* in_sizes, int n_in,
                              void* d_out, int out_size) {
    const float* feat    = (const float*)d_in[0];
    const float* pcoords = (const float*)d_in[1];
    const float* coarse  = (const float*)d_in[2];
    const float* coef_w  = (const float*)d_in[4];
    const float* coef_b  = (const float*)d_in[5];
    const float* freq_w  = (const float*)d_in[6];
    const float* freq_b  = (const float*)d_in[7];
    const float* phase_w = (const float*)d_in[8];
    const float* b0 = (const float*)d_in[10];
    const float* b1 = (const float*)d_in[12];
    const float* b2 = (const float*)d_in[14];
    const float* w3 = (const float*)d_in[15];
    const float* b3 = (const float*)d_in[16];
    float* out = (float*)d_out;

    prep_feat<<<(B_*HP*HP*C_ + 255)/256, 256>>>(feat);
    prep_wconv<<<(512*2304 + 255)/256, 256>>>(coef_w, coef_b, freq_w, freq_b);
    prep_wmlp<<<(3*65536 + 255)/256, 256>>>((const float*)d_in[9], (const float*)d_in[11],
                                            (const float*)d_in[13]);

    const int CSMEM = 2*CSTG*2;  // 81920 B
    cudaFuncSetAttribute(conv_mma_kernel, cudaFuncAttributeMaxDynamicSharedMemorySize, CSMEM);
    conv_mma_kernel<<<dim3(4, 128, 2), 256, CSMEM>>>();

    // point smem: Xh+Xl + weights(2 stages, hi only) + misc
    const int PSMEM = (MROWS*XP*2)*2 + (2*WSTG)*2
                    + (256 + 128*3 + 514 + 256)*4 + 128*2*4 + 64;
    cudaFuncSetAttribute(point_mma_kernel, cudaFuncAttributeMaxDynamicSharedMemorySize, PSMEM);
    point_mma_kernel<<<(B_*Q_)/NPTS, 512, PSMEM>>>(pcoords, phase_w,
                                                   b0, b1, b2, w3, b3,
                                                   coarse, out);
}

// round 7
// speedup vs baseline: 4.0522x; 1.2240x over previous
#include <cuda_runtime.h>
#include <cuda_bf16.h>
#include <cuda_fp16.h>
#include <cstdint>
#include <cstddef>

#define B_ 2
#define C_ 256
#define H_ 128
#define W_ 128
#define Q_ 32768
#define HP 130
#define HW_ (H_*W_)

// ---------------- static device scratch ----------------
__device__ __align__(16) __half g_Ah[(size_t)B_*HP*HP*C_];   // padded NHWC hi (fp16)
__device__ __align__(16) __half g_Al[(size_t)B_*HP*HP*C_];   // padded NHWC lo (fp16)
__device__ __align__(16) __half g_Wth[512*2304];             // conv W^T [oc][k] hi
__device__ __align__(16) __half g_Wtl[512*2304];             // lo
__device__ __align__(16) __half g_Mh[3*256*256];             // mlp W^T [l][n][k] fp16 (hi only)
__device__ float g_cbias[512];
__device__ __align__(16) float g_cf[(size_t)B_*HW_*512];     // conv out [b][pix][512] fp32

// ---------------- helpers ----------------
__device__ __forceinline__ uint32_t smem_u32(const void* p){
    return (uint32_t)__cvta_generic_to_shared(p);
}
__device__ __forceinline__ void ldsm4(uint32_t& r0,uint32_t& r1,uint32_t& r2,uint32_t& r3,uint32_t a){
    asm volatile("ldmatrix.sync.aligned.m8n8.x4.shared.b16 {%0,%1,%2,%3},[%4];"
        :"=r"(r0),"=r"(r1),"=r"(r2),"=r"(r3):"r"(a));
}
__device__ __forceinline__ void cp16(uint32_t d, const void* s){
    asm volatile("cp.async.ca.shared.global [%0],[%1],16;"::"r"(d),"l"(s));
}
__device__ __forceinline__ void cp_commit(){ asm volatile("cp.async.commit_group;"); }
// fp16 mma
__device__ __forceinline__ void mma16816h(float* c, const uint32_t* a, const uint32_t* b){
    asm volatile("mma.sync.aligned.m16n8k16.row.col.f32.f16.f16.f32 "
        "{%0,%1,%2,%3},{%4,%5,%6,%7},{%8,%9},{%0,%1,%2,%3};"
        : "+f"(c[0]),"+f"(c[1]),"+f"(c[2]),"+f"(c[3])
        : "r"(a[0]),"r"(a[1]),"r"(a[2]),"r"(a[3]),"r"(b[0]),"r"(b[1]));
}
__device__ __forceinline__ uint32_t pack_hi16(float2 v){
    __half2 h = __floats2half2_rn(v.x, v.y);
    return *reinterpret_cast<uint32_t*>(&h);
}

// ---------------- prep kernels ----------------
__global__ void prep_feat(const float* __restrict__ feat){
    int id = blockIdx.x*256 + threadIdx.x;
    if (id >= B_*HP*HP*C_) return;
    int c = id & 255; int rest = id >> 8;
    int xx = rest % HP; rest /= HP;
    int yy = rest % HP; int b = rest / HP;
    float v = 0.f;
    if (yy >= 1 && yy <= H_ && xx >= 1 && xx <= W_)
        v = feat[(((size_t)(b*C_ + c))*H_ + (yy-1))*W_ + (xx-1)];
    __half h = __float2half_rn(v);
    g_Ah[id] = h;
    g_Al[id] = __float2half_rn(v - __half2float(h));
}

__global__ void prep_wconv(const float* __restrict__ cw, const float* __restrict__ cb,
                           const float* __restrict__ fw, const float* __restrict__ fb){
    int id = blockIdx.x*256 + threadIdx.x;
    if (id < 512) g_cbias[id] = (id < 256) ? cb[id] : fb[id-256];
    if (id >= 512*2304) return;
    int oc = id / 2304, k = id % 2304;
    int tap = k >> 8, ic = k & 255;
    float v = (oc < 256) ? cw[(oc*256 + ic)*9 + tap]
                         : fw[((oc-256)*256 + ic)*9 + tap];
    __half h = __float2half_rn(v);
    g_Wth[id] = h;
    g_Wtl[id] = __float2half_rn(v - __half2float(h));
}

__global__ void prep_wmlp(const float* __restrict__ w0, const float* __restrict__ w1,
                          const float* __restrict__ w2){
    int id = blockIdx.x*256 + threadIdx.x;
    if (id >= 3*65536) return;
    int l = id >> 16, r = id & 65535;
    int n = r >> 8, k = r & 255;
    const float* w = (l==0) ? w0 : (l==1) ? w1 : w2;
    g_Mh[id] = __float2half_rn(w[k*256 + n]);
}

// ---------------- conv: dual 3x3 conv as implicit fp16 tensor GEMM ----------------
// block: 128 pixels (one image row) x 128 oc; K = 9*256 in steps of 32
// coef blocks (oc0 < 256): 2-term (Ah*Bh + Al*Bh)  -> exact-A x W-hi
// freq blocks (oc0 >= 256): 3-term (+ Ah*Bl)       -> ~2^-21 accurate
#define CARR (128*40)
#define CSTG (4*CARR)
__global__ __launch_bounds__(256) void conv_mma_kernel(){
    extern __shared__ __align__(16) __half cs[];
    const int t = threadIdx.x, warp = t>>5, lane = t&31;
    const int oc0 = blockIdx.x*128, y = blockIdx.y, b = blockIdx.z;
    const int m0 = (warp>>2)*64, n0 = (warp&3)*32;
    const bool three = (oc0 >= 256);     // freq half needs the W-lo term

    float acc[4][4][4];
    #pragma unroll
    for (int i=0;i<4;++i)
        #pragma unroll
        for (int j=0;j<4;++j)
            #pragma unroll
            for (int q=0;q<4;++q) acc[i][j][q] = 0.f;

    auto issue = [&](int s, int stg){
        const int tap = s >> 3, sub = s & 7;
        const int ky = tap/3, kx = tap - ky*3;
        const int k0 = tap*256 + sub*32;
        __half* dstb = cs + stg*CSTG;
        #pragma unroll
        for (int j=0;j<8;++j){
            int cid = t + j*256;
            int arr = cid >> 9, w = cid & 511, row = w >> 2, c = w & 3;
            uint32_t dst = smem_u32(dstb + arr*CARR + row*40 + c*8);
            const __half* src;
            if (arr == 0)      src = g_Ah + ((size_t)((b*HP + y+ky)*HP + row+kx))*C_ + sub*32 + c*8;
            else if (arr == 1) src = g_Al + ((size_t)((b*HP + y+ky)*HP + row+kx))*C_ + sub*32 + c*8;
            else if (arr == 2) src = g_Wth + (size_t)(oc0+row)*2304 + k0 + c*8;
            else               src = g_Wtl + (size_t)(oc0+row)*2304 + k0 + c*8;
            cp16(dst, src);
        }
        cp_commit();
    };

    issue(0, 0);
    for (int s = 0; s < 72; ++s){
        const int stg = s & 1;
        if (s+1 < 72) issue(s+1, (s+1)&1);
        if (s+1 < 72) asm volatile("cp.async.wait_group 1;");
        else          asm volatile("cp.async.wait_group 0;");
        __syncthreads();
        const __half* Ah = cs + stg*CSTG;
        const __half* Al = Ah + CARR;
        const __half* Bh = Al + CARR;
        const __half* Bl = Bh + CARR;
        const int rsel = lane & 15, kgrp = (lane >> 4)*8;
        #pragma unroll
        for (int k16 = 0; k16 < 32; k16 += 16){
            uint32_t ah[4][4], al[4][4], bh[4][2], bl[4][2];
            #pragma unroll
            for (int mi=0;mi<4;++mi){
                uint32_t a0 = smem_u32(Ah + (m0+mi*16+rsel)*40 + k16 + kgrp);
                ldsm4(ah[mi][0],ah[mi][1],ah[mi][2],ah[mi][3], a0);
                uint32_t a1 = smem_u32(Al + (m0+mi*16+rsel)*40 + k16 + kgrp);
                ldsm4(al[mi][0],al[mi][1],al[mi][2],al[mi][3], a1);
            }
            #pragma unroll
            for (int nj=0;nj<2;++nj){
                uint32_t r0,r1,r2,r3;
                uint32_t a0 = smem_u32(Bh + (n0+nj*16+rsel)*40 + k16 + kgrp);
                ldsm4(r0,r1,r2,r3,a0);
                bh[2*nj][0]=r0; bh[2*nj][1]=r2; bh[2*nj+1][0]=r1; bh[2*nj+1][1]=r3;
                uint32_t a1 = smem_u32(Bl + (n0+nj*16+rsel)*40 + k16 + kgrp);
                ldsm4(r0,r1,r2,r3,a1);
                bl[2*nj][0]=r0; bl[2*nj][1]=r2; bl[2*nj+1][0]=r1; bl[2*nj+1][1]=r3;
            }
            #pragma unroll
            for (int mi=0;mi<4;++mi)
                #pragma unroll
                for (int ni=0;ni<4;++ni){
                    mma16816h(acc[mi][ni], ah[mi], bh[ni]);
                    mma16816h(acc[mi][ni], al[mi], bh[ni]);
                    if (three) mma16816h(acc[mi][ni], ah[mi], bl[ni]);
                }
        }
        __syncthreads();
    }

    #pragma unroll
    for (int mi=0;mi<4;++mi){
        const int x = m0 + mi*16 + (lane>>2);
        #pragma unroll
        for (int ni=0;ni<4;++ni){
            const int col = oc0 + n0 + ni*8 + (lane&3)*2;
            float2 bb = *(const float2*)&g_cbias[col];
            float* o0 = g_cf + ((size_t)(b*HW_ + y*W_ + x))*512 + col;
            float* o1 = g_cf + ((size_t)(b*HW_ + y*W_ + x + 8))*512 + col;
            *(float2*)o0 = make_float2(acc[mi][ni][0]+bb.x, acc[mi][ni][1]+bb.y);
            *(float2*)o1 = make_float2(acc[mi][ni][2]+bb.x, acc[mi][ni][3]+bb.y);
        }
    }
}

// ---------------- point kernel: gather + sinusoid + 1-term fp16 tensor MLP ----------------
// block = 32 points x 4 shifts = 128 rows; 512 threads (16 warps)
// activations fp16 (single precision term); weights fp16 hi-only
#define MROWS 128
#define NPTS  32
#define XP    264                 // fp16 pitch for X rows (528B: conflict-free ldmatrix)
#define WP    40                  // fp16 pitch for 32-k weight chunk rows
#define WSTG  (256*WP)            // fp16 elems per stage
__global__ __launch_bounds__(512) void point_mma_kernel(
        const float* __restrict__ pc,
        const float* __restrict__ phase_w,
        const float* __restrict__ b0, const float* __restrict__ b1,
        const float* __restrict__ b2,
        const float* __restrict__ w3, const float* __restrict__ b3,
        const float* __restrict__ coarse,
        float* __restrict__ out) {
    extern __shared__ __align__(16) __half smh[];
    __half* Xh = smh;                          // 128*264
    __half* Wt = Xh + MROWS*XP;                // 2 stages * WSTG
    float* misc  = (float*)(Wt + 2*WSTG);
    float* ph     = misc;                  // 256
    float* s_rel0 = ph + 256;              // 128
    float* s_rel1 = s_rel0 + 128;          // 128
    float* s_area = s_rel1 + 128;          // 128
    int*   s_pix  = (int*)(s_area + 128);  // 128
    int*   s_phof = s_pix + 128;           // 128
    float* w3s    = (float*)(s_phof + 128);// 514
    float* s_pr   = w3s + 514;             // 256

    const int t = threadIdx.x, warp = t>>5, lane = t&31;
    const int g0 = blockIdx.x * NPTS;
    const int m0 = (warp>>2)*32, n0 = (warp&3)*64;
    const int rsel = lane & 15, kgrp = (lane >> 4)*8;

    // constants into smem
    if (t < 128) {
        float p0 = phase_w[2*t], p1 = phase_w[2*t+1];
        ph[t]       = fmaf(8.f,   p0, 8.f*p1);
        ph[128 + t] = fmaf(128.f, p0, 128.f*p1);
    }
    for (int i = t; i < 514; i += 512)
        w3s[i] = (i < 512) ? w3[i] : b3[i - 512];

    // stage 1: per-row pixel index / rel / area
    if (t < MROWS) {
        const int p_local = t >> 2, s = t & 3;
        const int g = g0 + p_local;
        const int q = g & (Q_ - 1);
        const float pc0 = pc[2*g], pc1 = pc[2*g + 1];
        const float SH_P = (float)( 1.0/128.0 + 1e-6);
        const float SH_M = (float)(-1.0/128.0 + 1e-6);
        const float LO = (float)(-1.0 + 1e-6), HI = (float)(1.0 - 1e-6);
        float cy = pc0 + ((s >= 2) ? SH_P : SH_M);
        float cx = pc1 + ((s & 1) ? SH_P : SH_M);
        cy = fminf(fmaxf(cy, LO), HI);
        cx = fminf(fmaxf(cx, LO), HI);
        int iy = (int)rintf(((cy + 1.f)*128.f - 1.f)*0.5f);
        int ix = (int)rintf(((cx + 1.f)*128.f - 1.f)*0.5f);
        iy = min(max(iy, 0), 127); ix = min(max(ix, 0), 127);
        float qcy = -0.9921875f + 0.015625f*(float)iy;
        float qcx = -0.9921875f + 0.015625f*(float)ix;
        float rel0 = (pc0 - qcy)*128.f;
        float rel1 = (pc1 - qcx)*128.f;
        s_pix[t]  = iy*W_ + ix;
        s_rel0[t] = rel0;  s_rel1[t] = rel1;
        s_area[t] = fabsf(rel0*rel1) + 1e-9f;
        s_phof[t] = (q < 2) ? 0 : 128;
    }
    __syncthreads();

    // weight prefetch: 24 chunks of k=32 (3 layers x 8), fp16 hi only
    auto wissue = [&](int g, int stg){
        const int L = g >> 3, s = g & 7;
        __half* dstb = Wt + stg*WSTG;
        const __half* srcb = g_Mh + L*65536 + s*32;
        #pragma unroll
        for (int j=0;j<2;++j){
            int cid = t + j*512;            // 0..1023
            int n = cid >> 2, c = cid & 3;
            uint32_t dst = smem_u32(dstb + n*WP + c*8);
            cp16(dst, srcb + n*256 + c*8);
        }
        cp_commit();
    };
    wissue(0, 0);

    // stage 2: gather + sinusoidal features -> Xh (fp16)
    {
        #pragma unroll 1
        for (int rr = 0; rr < 8; ++rr) {
            const int r = warp*8 + rr;
            const int g = g0 + (r >> 2);
            const int bb = g >> 15;
            const float* base = g_cf + ((size_t)(bb*HW_ + s_pix[r])) * 512;
            const float rel0 = s_rel0[r], rel1 = s_rel1[r];
            const float* php = ph + s_phof[r];
            #pragma unroll
            for (int i = 0; i < 2; ++i) {
                const int kp = lane + 32*i;       // pair index 0..63
                const int k0 = 2*kp;              // k in 0..126 even
                float4 f4 = *(const float4*)(base + 256 + 2*k0);   // freq pairs
                float2 cc = *(const float2*)(base + k0);            // coef (cos half)
                float2 cs2 = *(const float2*)(base + 128 + k0);     // coef (sin half)
                float2 ph2 = *(const float2*)(php + k0);
                float qf0 = fmaf(f4.x, rel0, fmaf(f4.y, rel1, ph2.x));
                float qf1 = fmaf(f4.z, rel0, fmaf(f4.w, rel1, ph2.y));
                float sv0, cv0, sv1, cv1;
                sincospif(qf0, &sv0, &cv0);
                sincospif(qf1, &sv1, &cv1);
                *(uint32_t*)&Xh[r*XP + k0]       = pack_hi16(make_float2(cc.x*cv0,  cc.y*cv1));
                *(uint32_t*)&Xh[r*XP + 128 + k0] = pack_hi16(make_float2(cs2.x*sv0, cs2.y*sv1));
            }
        }
    }

    // stage 3: 3 layers of 1-term fp16 tensor GEMM, K chunks of 32
    float acc[2][8][4];
    for (int g = 0; g < 24; ++g){
        const int L = g >> 3, kc = g & 7, stg = g & 1;
        if (kc == 0){
            #pragma unroll
            for (int i=0;i<2;++i)
                #pragma unroll
                for (int j=0;j<8;++j)
                    #pragma unroll
                    for (int q=0;q<4;++q) acc[i][j][q] = 0.f;
        }
        if (g+1 < 24) wissue(g+1, (g+1)&1);
        if (g+1 < 24) asm volatile("cp.async.wait_group 1;");
        else          asm volatile("cp.async.wait_group 0;");
        __syncthreads();

        const __half* WH = Wt + stg*WSTG;
        #pragma unroll
        for (int kh = 0; kh < 2; ++kh){
            const int k16 = kc*32 + kh*16;
            uint32_t AH[2][4];
            #pragma unroll
            for (int mi=0;mi<2;++mi){
                ldsm4(AH[mi][0],AH[mi][1],AH[mi][2],AH[mi][3],
                      smem_u32(Xh + (m0+mi*16+rsel)*XP + k16 + kgrp));
            }
            #pragma unroll
            for (int nj=0;nj<4;++nj){
                uint32_t r0,r1,r2,r3;
                ldsm4(r0,r1,r2,r3, smem_u32(WH + (n0+nj*16+rsel)*WP + kh*16 + kgrp));
                uint32_t b0r[2] = {r0, r2}, b1r[2] = {r1, r3};
                #pragma unroll
                for (int mi=0;mi<2;++mi){
                    mma16816h(acc[mi][2*nj],   AH[mi], b0r);
                    mma16816h(acc[mi][2*nj+1], AH[mi], b1r);
                }
            }
        }
        __syncthreads();

        if (kc == 7){
            // layer epilogue: relu(acc + bias) -> Xh in place (fp16)
            const float* bg = (L==0) ? b0 : (L==1) ? b1 : b2;
            #pragma unroll
            for (int mi=0;mi<2;++mi){
                const int r = m0 + mi*16 + (lane>>2);
                #pragma unroll
                for (int ni=0;ni<8;++ni){
                    const int c = n0 + ni*8 + (lane&3)*2;
                    float2 bb = *(const float2*)&bg[c];
                    *(uint32_t*)&Xh[r*XP + c] =
                        pack_hi16(make_float2(fmaxf(acc[mi][ni][0]+bb.x, 0.f),
                                              fmaxf(acc[mi][ni][1]+bb.y, 0.f)));
                    *(uint32_t*)&Xh[(r+8)*XP + c] =
                        pack_hi16(make_float2(fmaxf(acc[mi][ni][2]+bb.x, 0.f),
                                              fmaxf(acc[mi][ni][3]+bb.y, 0.f)));
                }
            }
            __syncthreads();
        }
    }

    // final 256->2 layer (fp32 accum from fp16 activations)
    if (t < 2*MROWS) {
        const int r = t >> 1, c = t & 1;
        const __half* rh = Xh + r*XP;
        float sum = w3s[512 + c];
        #pragma unroll 4
        for (int i = 0; i < 128; ++i) {
            uint32_t hu = *(const uint32_t*)&rh[2*i];
            __half2 hb = *reinterpret_cast<__half2*>(&hu);
            sum = fmaf(__half2float(hb.x), w3s[4*i + c], sum);
            sum = fmaf(__half2float(hb.y), w3s[4*i + 2 + c], sum);
        }
        s_pr[2*r + c] = sum;
    }
    __syncthreads();

    // local-ensemble combine + coarse residual
    if (t < 2*NPTS) {
        const int p = t >> 1, c = t & 1;
        const int rb = p*4;
        float a0 = s_area[rb+0], a1 = s_area[rb+1], a2 = s_area[rb+2], a3 = s_area[rb+3];
        float tot = a0 + a1 + a2 + a3;
        float v = s_pr[2*(rb+0)+c]*a3 + s_pr[2*(rb+1)+c]*a2
                + s_pr[2*(rb+2)+c]*a1 + s_pr[2*(rb+3)+c]*a0;
        v /= tot;
        const int g = g0 + p;
        const int bb = g >> 15, q = g & (Q_ - 1);
        const int oidx = (bb*2 + c)*Q_ + q;
        out[oidx] = v + coarse[oidx];
    }
}

// ---------------- launch ----------------
extern "C" void kernel_launch(void* const* d_in, const int* in_sizes, int n_in,
                              void* d_out, int out_size) {
    const float* feat    = (const float*)d_in[0];
    const float* pcoords = (const float*)d_in[1];
    const float* coarse  = (const float*)d_in[2];
    const float* coef_w  = (const float*)d_in[4];
    const float* coef_b  = (const float*)d_in[5];
    const float* freq_w  = (const float*)d_in[6];
    const float* freq_b  = (const float*)d_in[7];
    const float* phase_w = (const float*)d_in[8];
    const float* b0 = (const float*)d_in[10];
    const float* b1 = (const float*)d_in[12];
    const float* b2 = (const float*)d_in[14];
    const float* w3 = (const float*)d_in[15];
    const float* b3 = (const float*)d_in[16];
    float* out = (float*)d_out;

    prep_feat<<<(B_*HP*HP*C_ + 255)/256, 256>>>(feat);
    prep_wconv<<<(512*2304 + 255)/256, 256>>>(coef_w, coef_b, freq_w, freq_b);
    prep_wmlp<<<(3*65536 + 255)/256, 256>>>((const float*)d_in[9], (const float*)d_in[11],
                                            (const float*)d_in[13]);

    const int CSMEM = 2*CSTG*2;  // 81920 B
    cudaFuncSetAttribute(conv_mma_kernel, cudaFuncAttributeMaxDynamicSharedMemorySize, CSMEM);
    conv_mma_kernel<<<dim3(4, 128, 2), 256, CSMEM>>>();

    // point smem: Xh + weights(2 stages, hi only) + misc
    const int PSMEM = (MROWS*XP)*2 + (2*WSTG)*2
                    + (256 + 128*3 + 514 + 256)*4 + 128*2*4 + 64;
    cudaFuncSetAttribute(point_mma_kernel, cudaFuncAttributeMaxDynamicSharedMemorySize, PSMEM);
    point_mma_kernel<<<(B_*Q_)/NPTS, 512, PSMEM>>>(pcoords, phase_w,
                                                   b0, b1, b2, w3, b3,
                                                   coarse, out);
}

// round 8
// speedup vs baseline: 4.5846x; 1.1314x over previous
#include <cuda_runtime.h>
#include <cuda_bf16.h>
#include <cuda_fp16.h>
#include <cstdint>
#include <cstddef>

#define B_ 2
#define C_ 256
#define H_ 128
#define W_ 128
#define Q_ 32768
#define HP 130
#define HW_ (H_*W_)

// ---------------- static device scratch ----------------
__device__ __align__(16) __half g_Ah[(size_t)B_*HP*HP*C_];   // padded NHWC hi (fp16)
__device__ __align__(16) __half g_Al[(size_t)B_*HP*HP*C_];   // padded NHWC lo (fp16)
__device__ __align__(16) __half g_Wth[512*2304];             // conv W^T [oc][k] hi
__device__ __align__(16) __half g_Wtl[512*2304];             // lo
__device__ __align__(16) __half g_Mh[3*256*256];             // mlp W^T [l][n][k] fp16
__device__ float g_cbias[512];
__device__ __align__(16) float g_cf[(size_t)B_*HW_*512];     // conv out [b][pix][512] fp32

// ---------------- helpers ----------------
__device__ __forceinline__ uint32_t smem_u32(const void* p){
    return (uint32_t)__cvta_generic_to_shared(p);
}
__device__ __forceinline__ void ldsm4(uint32_t& r0,uint32_t& r1,uint32_t& r2,uint32_t& r3,uint32_t a){
    asm volatile("ldmatrix.sync.aligned.m8n8.x4.shared.b16 {%0,%1,%2,%3},[%4];"
        :"=r"(r0),"=r"(r1),"=r"(r2),"=r"(r3):"r"(a));
}
__device__ __forceinline__ void cp16(uint32_t d, const void* s){
    asm volatile("cp.async.ca.shared.global [%0],[%1],16;"::"r"(d),"l"(s));
}
__device__ __forceinline__ void cp_commit(){ asm volatile("cp.async.commit_group;"); }
__device__ __forceinline__ void mma16816h(float* c, const uint32_t* a, const uint32_t* b){
    asm volatile("mma.sync.aligned.m16n8k16.row.col.f32.f16.f16.f32 "
        "{%0,%1,%2,%3},{%4,%5,%6,%7},{%8,%9},{%0,%1,%2,%3};"
        : "+f"(c[0]),"+f"(c[1]),"+f"(c[2]),"+f"(c[3])
        : "r"(a[0]),"r"(a[1]),"r"(a[2]),"r"(a[3]),"r"(b[0]),"r"(b[1]));
}
__device__ __forceinline__ uint32_t pack_hi16(float2 v){
    __half2 h = __floats2half2_rn(v.x, v.y);
    return *reinterpret_cast<uint32_t*>(&h);
}
// fast sin/cos of pi*x: rint range reduction + Taylor (abs err < 4e-6)
__device__ __forceinline__ void sincospif_fast(float x, float* sp, float* cp){
    float n = rintf(x);
    float r = x - n;
    float r2 = r*r;
    float s = fmaf(r2, 0.08214588661f, -0.5992645293f);
    s = fmaf(r2, s, 2.550164040f);
    s = fmaf(r2, s, -5.167712780f);
    s = fmaf(r2, s, 3.14159265359f);
    s *= r;
    float c = fmaf(r2, -0.02580689139f, 0.2353306304f);
    c = fmaf(r2, c, -1.335262769f);
    c = fmaf(r2, c, 4.058712126f);
    c = fmaf(r2, c, -4.934802201f);
    c = fmaf(r2, c, 1.0f);
    uint32_t sg = ((uint32_t)(int)n) << 31;
    *sp = __uint_as_float(__float_as_uint(s) ^ sg);
    *cp = __uint_as_float(__float_as_uint(c) ^ sg);
}

// ---------------- prep kernels ----------------
__global__ void prep_feat(const float* __restrict__ feat){
    int id = blockIdx.x*256 + threadIdx.x;
    if (id >= B_*HP*HP*C_) return;
    int c = id & 255; int rest = id >> 8;
    int xx = rest % HP; rest /= HP;
    int yy = rest % HP; int b = rest / HP;
    float v = 0.f;
    if (yy >= 1 && yy <= H_ && xx >= 1 && xx <= W_)
        v = feat[(((size_t)(b*C_ + c))*H_ + (yy-1))*W_ + (xx-1)];
    __half h = __float2half_rn(v);
    g_Ah[id] = h;
    g_Al[id] = __float2half_rn(v - __half2float(h));
}

__global__ void prep_wconv(const float* __restrict__ cw, const float* __restrict__ cb,
                           const float* __restrict__ fw, const float* __restrict__ fb){
    int id = blockIdx.x*256 + threadIdx.x;
    if (id < 512) g_cbias[id] = (id < 256) ? cb[id] : fb[id-256];
    if (id >= 512*2304) return;
    int oc = id / 2304, k = id % 2304;
    int tap = k >> 8, ic = k & 255;
    float v = (oc < 256) ? cw[(oc*256 + ic)*9 + tap]
                         : fw[((oc-256)*256 + ic)*9 + tap];
    __half h = __float2half_rn(v);
    g_Wth[id] = h;
    g_Wtl[id] = __float2half_rn(v - __half2float(h));
}

__global__ void prep_wmlp(const float* __restrict__ w0, const float* __restrict__ w1,
                          const float* __restrict__ w2){
    int id = blockIdx.x*256 + threadIdx.x;
    if (id >= 3*65536) return;
    int l = id >> 16, r = id & 65535;
    int n = r >> 8, k = r & 255;
    const float* w = (l==0) ? w0 : (l==1) ? w1 : w2;
    g_Mh[id] = __float2half_rn(w[k*256 + n]);
}

// ---------------- conv: block 128px x 256oc, warp tile 64x64, 3-stage pipeline ----------------
// blockIdx.x: 0 = coef (1-term: Ah*Bh), 1 = freq (3-term: Ah*Bh + Al*Bh + Ah*Bl)
#define ST_AH 0
#define ST_AL 5120
#define ST_BH 10240
#define ST_BL 20480
#define ST_SZ 30720                 // halves per stage (61440 B)
__global__ __launch_bounds__(256) void conv_mma_kernel(){
    extern __shared__ __align__(16) __half cs[];
    const int t = threadIdx.x, warp = t>>5, lane = t&31;
    const int oc0 = blockIdx.x*256, y = blockIdx.y, b = blockIdx.z;
    const bool three = (blockIdx.x == 1);
    const int m0 = (warp>>2)*64, n0 = (warp&3)*64;
    const int rsel = lane & 15, kgrp = (lane >> 4)*8;

    float acc[4][8][4];
    #pragma unroll
    for (int i=0;i<4;++i)
        #pragma unroll
        for (int j=0;j<8;++j)
            #pragma unroll
            for (int q=0;q<4;++q) acc[i][j][q] = 0.f;

    auto issue = [&](int s, int buf){
        const int tap = s >> 3, sub = s & 7;
        const int ky = tap/3, kx = tap - ky*3;
        const int k0 = tap*256 + sub*32;
        __half* dstb = cs + buf*ST_SZ;
        #pragma unroll
        for (int j=0;j<12;++j){
            if (j>=2 && j<4 && !three) continue;     // Al only for freq
            if (j>=8 && !three) continue;            // Bl only for freq
            int cid = t + j*256;
            uint32_t dst; const __half* src;
            if (j < 4){
                int w = cid & 511, row = w >> 2, ch = w & 3;
                const __half* base = (j < 2) ? g_Ah : g_Al;
                src = base + ((size_t)((b*HP + y+ky)*HP + row + kx))*C_ + sub*32 + ch*8;
                dst = smem_u32(dstb + ((j<2)?ST_AH:ST_AL) + row*40 + ch*8);
            } else {
                int w = cid & 1023, row = w >> 2, ch = w & 3;
                const __half* base = (j < 8) ? g_Wth : g_Wtl;
                src = base + (size_t)(oc0 + row)*2304 + k0 + ch*8;
                dst = smem_u32(dstb + ((j<8)?ST_BH:ST_BL) + row*40 + ch*8);
            }
            cp16(dst, src);
        }
        cp_commit();
    };

    issue(0, 0); issue(1, 1);
    asm volatile("cp.async.wait_group 1;");
    __syncthreads();

    for (int s = 0; s < 72; ++s){
        const int buf = s % 3;
        if (s + 2 < 72) issue(s + 2, (s + 2) % 3);
        const __half* Ah = cs + buf*ST_SZ + ST_AH;
        const __half* Al = cs + buf*ST_SZ + ST_AL;
        const __half* Bh = cs + buf*ST_SZ + ST_BH;
        const __half* Bl = cs + buf*ST_SZ + ST_BL;
        #pragma unroll
        for (int k16 = 0; k16 < 32; k16 += 16){
            uint32_t ah[4][4], al[4][4];
            #pragma unroll
            for (int mi=0;mi<4;++mi){
                ldsm4(ah[mi][0],ah[mi][1],ah[mi][2],ah[mi][3],
                      smem_u32(Ah + (m0+mi*16+rsel)*40 + k16 + kgrp));
                if (three)
                    ldsm4(al[mi][0],al[mi][1],al[mi][2],al[mi][3],
                          smem_u32(Al + (m0+mi*16+rsel)*40 + k16 + kgrp));
            }
            #pragma unroll
            for (int nj=0;nj<4;++nj){
                uint32_t r0,r1,r2,r3;
                ldsm4(r0,r1,r2,r3, smem_u32(Bh + (n0+nj*16+rsel)*40 + k16 + kgrp));
                uint32_t bh0[2] = {r0, r2}, bh1[2] = {r1, r3};
                if (three){
                    uint32_t q0,q1,q2,q3;
                    ldsm4(q0,q1,q2,q3, smem_u32(Bl + (n0+nj*16+rsel)*40 + k16 + kgrp));
                    uint32_t bl0[2] = {q0, q2}, bl1[2] = {q1, q3};
                    #pragma unroll
                    for (int mi=0;mi<4;++mi){
                        mma16816h(acc[mi][2*nj],   ah[mi], bh0);
                        mma16816h(acc[mi][2*nj],   al[mi], bh0);
                        mma16816h(acc[mi][2*nj],   ah[mi], bl0);
                        mma16816h(acc[mi][2*nj+1], ah[mi], bh1);
                        mma16816h(acc[mi][2*nj+1], al[mi], bh1);
                        mma16816h(acc[mi][2*nj+1], ah[mi], bl1);
                    }
                } else {
                    #pragma unroll
                    for (int mi=0;mi<4;++mi){
                        mma16816h(acc[mi][2*nj],   ah[mi], bh0);
                        mma16816h(acc[mi][2*nj+1], ah[mi], bh1);
                    }
                }
            }
        }
        if (s < 71){
            if (s + 2 < 72) asm volatile("cp.async.wait_group 1;");
            else            asm volatile("cp.async.wait_group 0;");
            __syncthreads();
        }
    }

    #pragma unroll
    for (int mi=0;mi<4;++mi){
        const int x = m0 + mi*16 + (lane>>2);
        #pragma unroll
        for (int ni=0;ni<8;++ni){
            const int col = oc0 + n0 + ni*8 + (lane&3)*2;
            float2 bb = *(const float2*)&g_cbias[col];
            float* o0 = g_cf + ((size_t)(b*HW_ + y*W_ + x))*512 + col;
            float* o1 = g_cf + ((size_t)(b*HW_ + y*W_ + x + 8))*512 + col;
            *(float2*)o0 = make_float2(acc[mi][ni][0]+bb.x, acc[mi][ni][1]+bb.y);
            *(float2*)o1 = make_float2(acc[mi][ni][2]+bb.x, acc[mi][ni][3]+bb.y);
        }
    }
}

// ---------------- point kernel: gather + sinusoid + 1-term fp16 tensor MLP ----------------
// block = 32 points x 4 shifts = 128 rows; 512 threads (16 warps)
// K chunks of 64 (12 stages), 1 sync/stage (+1 at layer boundaries)
#define MROWS 128
#define NPTS  32
#define XP    264                 // fp16 pitch for X rows
#define WP2   72                  // fp16 pitch for 64-k weight chunk rows (144B, odd*16B)
#define WSTG2 (256*WP2)           // fp16 elems per stage
__global__ __launch_bounds__(512) void point_mma_kernel(
        const float* __restrict__ pc,
        const float* __restrict__ phase_w,
        const float* __restrict__ b0, const float* __restrict__ b1,
        const float* __restrict__ b2,
        const float* __restrict__ w3, const float* __restrict__ b3,
        const float* __restrict__ coarse,
        float* __restrict__ out) {
    extern __shared__ __align__(16) __half smh[];
    __half* Xh = smh;                          // 128*264
    __half* Wt = Xh + MROWS*XP;                // 2 stages * WSTG2
    float* misc  = (float*)(Wt + 2*WSTG2);
    float* ph     = misc;                  // 256
    float* s_rel0 = ph + 256;              // 128
    float* s_rel1 = s_rel0 + 128;          // 128
    float* s_area = s_rel1 + 128;          // 128
    int*   s_pix  = (int*)(s_area + 128);  // 128
    int*   s_phof = s_pix + 128;           // 128
    float* w3s    = (float*)(s_phof + 128);// 514
    float* s_pr   = w3s + 514;             // 256

    const int t = threadIdx.x, warp = t>>5, lane = t&31;
    const int g0 = blockIdx.x * NPTS;
    const int m0 = (warp>>2)*32, n0 = (warp&3)*64;
    const int rsel = lane & 15, kgrp = (lane >> 4)*8;

    if (t < 128) {
        float p0 = phase_w[2*t], p1 = phase_w[2*t+1];
        ph[t]       = fmaf(8.f,   p0, 8.f*p1);
        ph[128 + t] = fmaf(128.f, p0, 128.f*p1);
    }
    for (int i = t; i < 514; i += 512)
        w3s[i] = (i < 512) ? w3[i] : b3[i - 512];

    // stage 1: per-row pixel index / rel / area
    if (t < MROWS) {
        const int p_local = t >> 2, s = t & 3;
        const int g = g0 + p_local;
        const int q = g & (Q_ - 1);
        const float pc0 = pc[2*g], pc1 = pc[2*g + 1];
        const float SH_P = (float)( 1.0/128.0 + 1e-6);
        const float SH_M = (float)(-1.0/128.0 + 1e-6);
        const float LO = (float)(-1.0 + 1e-6), HI = (float)(1.0 - 1e-6);
        float cy = pc0 + ((s >= 2) ? SH_P : SH_M);
        float cx = pc1 + ((s & 1) ? SH_P : SH_M);
        cy = fminf(fmaxf(cy, LO), HI);
        cx = fminf(fmaxf(cx, LO), HI);
        int iy = (int)rintf(((cy + 1.f)*128.f - 1.f)*0.5f);
        int ix = (int)rintf(((cx + 1.f)*128.f - 1.f)*0.5f);
        iy = min(max(iy, 0), 127); ix = min(max(ix, 0), 127);
        float qcy = -0.9921875f + 0.015625f*(float)iy;
        float qcx = -0.9921875f + 0.015625f*(float)ix;
        float rel0 = (pc0 - qcy)*128.f;
        float rel1 = (pc1 - qcx)*128.f;
        s_pix[t]  = iy*W_ + ix;
        s_rel0[t] = rel0;  s_rel1[t] = rel1;
        s_area[t] = fabsf(rel0*rel1) + 1e-9f;
        s_phof[t] = (q < 2) ? 0 : 128;
    }
    __syncthreads();

    // weight prefetch: 12 chunks of k=64 (3 layers x 4)
    auto wissue = [&](int g, int stg){
        const int L = g >> 2, kc = g & 3;
        __half* dstb = Wt + stg*WSTG2;
        const __half* srcb = g_Mh + L*65536 + kc*64;
        #pragma unroll
        for (int j=0;j<4;++j){
            int cid = t + j*512;            // 0..2047
            int row = cid >> 3, ch = cid & 7;
            cp16(smem_u32(dstb + row*WP2 + ch*8), srcb + row*256 + ch*8);
        }
        cp_commit();
    };
    wissue(0, 0);

    // stage 2: gather + sinusoidal features -> Xh (fp16)
    {
        #pragma unroll 1
        for (int rr = 0; rr < 8; ++rr) {
            const int r = warp*8 + rr;
            const int g = g0 + (r >> 2);
            const int bb = g >> 15;
            const float* base = g_cf + ((size_t)(bb*HW_ + s_pix[r])) * 512;
            const float rel0 = s_rel0[r], rel1 = s_rel1[r];
            const float* php = ph + s_phof[r];
            #pragma unroll
            for (int i = 0; i < 2; ++i) {
                const int kp = lane + 32*i;
                const int k0 = 2*kp;
                float4 f4 = *(const float4*)(base + 256 + 2*k0);
                float2 cc = *(const float2*)(base + k0);
                float2 cs2 = *(const float2*)(base + 128 + k0);
                float2 ph2 = *(const float2*)(php + k0);
                float qf0 = fmaf(f4.x, rel0, fmaf(f4.y, rel1, ph2.x));
                float qf1 = fmaf(f4.z, rel0, fmaf(f4.w, rel1, ph2.y));
                float sv0, cv0, sv1, cv1;
                sincospif_fast(qf0, &sv0, &cv0);
                sincospif_fast(qf1, &sv1, &cv1);
                *(uint32_t*)&Xh[r*XP + k0]       = pack_hi16(make_float2(cc.x*cv0,  cc.y*cv1));
                *(uint32_t*)&Xh[r*XP + 128 + k0] = pack_hi16(make_float2(cs2.x*sv0, cs2.y*sv1));
            }
        }
    }
    asm volatile("cp.async.wait_group 0;");
    __syncthreads();    // X visible + W(0) visible

    // stage 3: 12 stages (3 layers x 4 k-chunks of 64)
    float acc[2][8][4];
    for (int g = 0; g < 12; ++g){
        const int L = g >> 2, kc = g & 3, stg = g & 1;
        if (kc == 0){
            #pragma unroll
            for (int i=0;i<2;++i)
                #pragma unroll
                for (int j=0;j<8;++j)
                    #pragma unroll
                    for (int q=0;q<4;++q) acc[i][j][q] = 0.f;
        }
        if (g+1 < 12) wissue(g+1, (g+1)&1);

        const __half* WH = Wt + stg*WSTG2;
        #pragma unroll
        for (int kh = 0; kh < 4; ++kh){
            const int k16 = kc*64 + kh*16;
            uint32_t AH[2][4];
            #pragma unroll
            for (int mi=0;mi<2;++mi){
                ldsm4(AH[mi][0],AH[mi][1],AH[mi][2],AH[mi][3],
                      smem_u32(Xh + (m0+mi*16+rsel)*XP + k16 + kgrp));
            }
            #pragma unroll
            for (int nj=0;nj<4;++nj){
                uint32_t r0,r1,r2,r3;
                ldsm4(r0,r1,r2,r3, smem_u32(WH + (n0+nj*16+rsel)*WP2 + kh*16 + kgrp));
                uint32_t b0r[2] = {r0, r2}, b1r[2] = {r1, r3};
                #pragma unroll
                for (int mi=0;mi<2;++mi){
                    mma16816h(acc[mi][2*nj],   AH[mi], b0r);
                    mma16816h(acc[mi][2*nj+1], AH[mi], b1r);
                }
            }
        }

        if (kc == 3){
            __syncthreads();   // all X reads of this layer done before overwrite
            const float* bg = (L==0) ? b0 : (L==1) ? b1 : b2;
            #pragma unroll
            for (int mi=0;mi<2;++mi){
                const int r = m0 + mi*16 + (lane>>2);
                #pragma unroll
                for (int ni=0;ni<8;++ni){
                    const int c = n0 + ni*8 + (lane&3)*2;
                    float2 bb = *(const float2*)&bg[c];
                    *(uint32_t*)&Xh[r*XP + c] =
                        pack_hi16(make_float2(fmaxf(acc[mi][ni][0]+bb.x, 0.f),
                                              fmaxf(acc[mi][ni][1]+bb.y, 0.f)));
                    *(uint32_t*)&Xh[(r+8)*XP + c] =
                        pack_hi16(make_float2(fmaxf(acc[mi][ni][2]+bb.x, 0.f),
                                              fmaxf(acc[mi][ni][3]+bb.y, 0.f)));
                }
            }
        }
        asm volatile("cp.async.wait_group 0;");
        __syncthreads();
    }

    // final 256->2 layer (fp32 accum from fp16 activations)
    if (t < 2*MROWS) {
        const int r = t >> 1, c = t & 1;
        const __half* rh = Xh + r*XP;
        float sum = w3s[512 + c];
        #pragma unroll 4
        for (int i = 0; i < 128; ++i) {
            uint32_t hu = *(const uint32_t*)&rh[2*i];
            __half2 hb = *reinterpret_cast<__half2*>(&hu);
            sum = fmaf(__half2float(hb.x), w3s[4*i + c], sum);
            sum = fmaf(__half2float(hb.y), w3s[4*i + 2 + c], sum);
        }
        s_pr[2*r + c] = sum;
    }
    __syncthreads();

    // local-ensemble combine + coarse residual
    if (t < 2*NPTS) {
        const int p = t >> 1, c = t & 1;
        const int rb = p*4;
        float a0 = s_area[rb+0], a1 = s_area[rb+1], a2 = s_area[rb+2], a3 = s_area[rb+3];
        float tot = a0 + a1 + a2 + a3;
        float v = s_pr[2*(rb+0)+c]*a3 + s_pr[2*(rb+1)+c]*a2
                + s_pr[2*(rb+2)+c]*a1 + s_pr[2*(rb+3)+c]*a0;
        v /= tot;
        const int g = g0 + p;
        const int bb = g >> 15, q = g & (Q_ - 1);
        const int oidx = (bb*2 + c)*Q_ + q;
        out[oidx] = v + coarse[oidx];
    }
}

// ---------------- launch ----------------
extern "C" void kernel_launch(void* const* d_in, const int* in_sizes, int n_in,
                              void* d_out, int out_size) {
    const float* feat    = (const float*)d_in[0];
    const float* pcoords = (const float*)d_in[1];
    const float* coarse  = (const float*)d_in[2];
    const float* coef_w  = (const float*)d_in[4];
    const float* coef_b  = (const float*)d_in[5];
    const float* freq_w  = (const float*)d_in[6];
    const float* freq_b  = (const float*)d_in[7];
    const float* phase_w = (const float*)d_in[8];
    const float* b0 = (const float*)d_in[10];
    const float* b1 = (const float*)d_in[12];
    const float* b2 = (const float*)d_in[14];
    const float* w3 = (const float*)d_in[15];
    const float* b3 = (const float*)d_in[16];
    float* out = (float*)d_out;

    prep_feat<<<(B_*HP*HP*C_ + 255)/256, 256>>>(feat);
    prep_wconv<<<(512*2304 + 255)/256, 256>>>(coef_w, coef_b, freq_w, freq_b);
    prep_wmlp<<<(3*65536 + 255)/256, 256>>>((const float*)d_in[9], (const float*)d_in[11],
                                            (const float*)d_in[13]);

    const int CSMEM = 3*ST_SZ*2;       // 184320 B
    cudaFuncSetAttribute(conv_mma_kernel, cudaFuncAttributeMaxDynamicSharedMemorySize, CSMEM);
    conv_mma_kernel<<<dim3(2, 128, 2), 256, CSMEM>>>();

    const int PSMEM = (MROWS*XP)*2 + (2*WSTG2)*2
                    + (256 + 128*3 + 514 + 256)*4 + 128*2*4 + 64;
    cudaFuncSetAttribute(point_mma_kernel, cudaFuncAttributeMaxDynamicSharedMemorySize, PSMEM);
    point_mma_kernel<<<(B_*Q_)/NPTS, 512, PSMEM>>>(pcoords, phase_w,
                                                   b0, b1, b2, w3, b3,
                                                   coarse, out);
}